// round 10
// baseline (speedup 1.0000x reference)
#include <cuda_runtime.h>
#include <cuda_bf16.h>
#include <cstdint>

// ---------------------------------------------------------------------------
// MultiHeadAttention: warp-mma bf16x3 projections + fused flash attention
// R10: R7 design (2 CTAs/SM) with K-tile loader coverage bug fixed
// ---------------------------------------------------------------------------

#define BATCH   2
#define SEQ     2048
#define DMODEL  1024
#define HEADS   16
#define KDIM    64
#define MTOT    (BATCH * SEQ)           // 4096

__device__ float g_Q[MTOT * DMODEL + 256];
__device__ float g_K[MTOT * DMODEL + 256];
__device__ float g_V[MTOT * DMODEL + 256];
__device__ float g_O[MTOT * DMODEL + 256];

// ======================= helpers ===========================================
__device__ __forceinline__ uint32_t smem_u32_of(const void* p) {
    uint32_t a;
    asm("{ .reg .u64 t; cvta.to.shared.u64 t, %1; cvt.u32.u64 %0, t; }"
        : "=r"(a) : "l"(p));
    return a;
}

__device__ __forceinline__ void ldmatrix_x4(uint32_t* r, uint32_t addr) {
    asm volatile("ldmatrix.sync.aligned.m8n8.x4.shared.b16 {%0,%1,%2,%3}, [%4];"
        : "=r"(r[0]), "=r"(r[1]), "=r"(r[2]), "=r"(r[3]) : "r"(addr));
}

__device__ __forceinline__ void mma_bf16(float* c, const uint32_t* a, const uint32_t* b) {
    asm volatile(
        "mma.sync.aligned.m16n8k16.row.col.f32.bf16.bf16.f32 "
        "{%0,%1,%2,%3}, {%4,%5,%6,%7}, {%8,%9}, {%0,%1,%2,%3};"
        : "+f"(c[0]), "+f"(c[1]), "+f"(c[2]), "+f"(c[3])
        : "r"(a[0]), "r"(a[1]), "r"(a[2]), "r"(a[3]), "r"(b[0]), "r"(b[1]));
}

__device__ __forceinline__ void st128(uint32_t addr, uint32_t a, uint32_t b,
                                      uint32_t c, uint32_t d) {
    asm volatile("st.shared.v4.b32 [%0], {%1,%2,%3,%4};"
                 :: "r"(addr), "r"(a), "r"(b), "r"(c), "r"(d) : "memory");
}
__device__ __forceinline__ void sts32(uint32_t addr, uint32_t a) {
    asm volatile("st.shared.u32 [%0], %1;" :: "r"(addr), "r"(a) : "memory");
}

__device__ __forceinline__ float ex2(float x) {
    float r;
    asm("ex2.approx.ftz.f32 %0, %1;" : "=f"(r) : "f"(x));
    return r;
}

__device__ __forceinline__ void split2(float x, float y, uint32_t& hi, uint32_t& lo) {
    __nv_bfloat16 hx = __float2bfloat16(x);
    __nv_bfloat16 hy = __float2bfloat16(y);
    __nv_bfloat162 h; h.x = hx; h.y = hy;
    hi = *reinterpret_cast<uint32_t*>(&h);
    __nv_bfloat162 l = __floats2bfloat162_rn(x - __bfloat162float(hx),
                                             y - __bfloat162float(hy));
    lo = *reinterpret_cast<uint32_t*>(&l);
}

// ======================= warp-MMA GEMM (projections) =======================
// C[m,n] = sum_k A[m,k] * B[n,k]. Tile 128x128, K-chunk 32, 256 thr (4x2 warps).
// launch_bounds(256,2): force <=128 regs -> 2 CTAs/SM.
#define LDSR 40

__global__ __launch_bounds__(256, 2)
void gemm_mma(const float* __restrict__ A, const float* __restrict__ B,
              float* __restrict__ C, int K, int lda, int ldb, int ldc)
{
    __shared__ __align__(16) uint16_t As_hi[128 * LDSR];
    __shared__ __align__(16) uint16_t As_lo[128 * LDSR];
    __shared__ __align__(16) uint16_t Bs_hi[128 * LDSR];
    __shared__ __align__(16) uint16_t Bs_lo[128 * LDSR];

    const int tid  = threadIdx.x;
    const int wid  = tid >> 5;
    const int lane = tid & 31;
    const int m0   = blockIdx.y * 128;
    const int n0   = blockIdx.x * 128;
    const int warp_m = wid & 3;
    const int warp_n = wid >> 2;

    float acc[2][8][4];
    #pragma unroll
    for (int i = 0; i < 2; i++)
        #pragma unroll
        for (int j = 0; j < 8; j++)
            #pragma unroll
            for (int q = 0; q < 4; q++) acc[i][j][q] = 0.f;

    const uint32_t sAhi = smem_u32_of(As_hi), sAlo = smem_u32_of(As_lo);
    const uint32_t sBhi = smem_u32_of(Bs_hi), sBlo = smem_u32_of(Bs_lo);

    const int r    = tid >> 1;
    const int kseg = (tid & 1) * 16;
    const float* pA = A + (long)(m0 + r) * lda + kseg;
    const float* pB = B + (long)(n0 + r) * ldb + kseg;
    const uint32_t ad = (uint32_t)(r * LDSR + kseg) * 2;

    for (int k0 = 0; k0 < K; k0 += 32) {
        {
            uint32_t hi[8], lo[8];
            #pragma unroll
            for (int i = 0; i < 4; i++) {
                float4 v = *reinterpret_cast<const float4*>(pA + k0 + i * 4);
                split2(v.x, v.y, hi[2 * i],     lo[2 * i]);
                split2(v.z, v.w, hi[2 * i + 1], lo[2 * i + 1]);
            }
            st128(sAhi + ad,      hi[0], hi[1], hi[2], hi[3]);
            st128(sAhi + ad + 16, hi[4], hi[5], hi[6], hi[7]);
            st128(sAlo + ad,      lo[0], lo[1], lo[2], lo[3]);
            st128(sAlo + ad + 16, lo[4], lo[5], lo[6], lo[7]);
            #pragma unroll
            for (int i = 0; i < 4; i++) {
                float4 v = *reinterpret_cast<const float4*>(pB + k0 + i * 4);
                split2(v.x, v.y, hi[2 * i],     lo[2 * i]);
                split2(v.z, v.w, hi[2 * i + 1], lo[2 * i + 1]);
            }
            st128(sBhi + ad,      hi[0], hi[1], hi[2], hi[3]);
            st128(sBhi + ad + 16, hi[4], hi[5], hi[6], hi[7]);
            st128(sBlo + ad,      lo[0], lo[1], lo[2], lo[3]);
            st128(sBlo + ad + 16, lo[4], lo[5], lo[6], lo[7]);
        }
        __syncthreads();

        #pragma unroll
        for (int ks = 0; ks < 32; ks += 16) {
            uint32_t ah[2][4], al[2][4];
            #pragma unroll
            for (int mi = 0; mi < 2; mi++) {
                const int row = warp_m * 32 + mi * 16 + (lane & 15);
                const int col = ks + (lane >> 4) * 8;
                const uint32_t off = (uint32_t)(row * LDSR + col) * 2;
                ldmatrix_x4(ah[mi], sAhi + off);
                ldmatrix_x4(al[mi], sAlo + off);
            }
            #pragma unroll
            for (int ng = 0; ng < 4; ng++) {
                const int nb   = warp_n * 64 + ng * 16;
                const int nrow = nb + (lane & 7) + ((lane >> 4) << 3);
                const int kcol = ks + ((lane >> 3) & 1) * 8;
                const uint32_t off = (uint32_t)(nrow * LDSR + kcol) * 2;
                uint32_t bh[4], bl[4];
                ldmatrix_x4(bh, sBhi + off);
                ldmatrix_x4(bl, sBlo + off);
                #pragma unroll
                for (int mi = 0; mi < 2; mi++) {
                    #pragma unroll
                    for (int nt = 0; nt < 2; nt++) {
                        float* c = acc[mi][ng * 2 + nt];
                        mma_bf16(c, ah[mi], bh + nt * 2);
                        mma_bf16(c, ah[mi], bl + nt * 2);
                        mma_bf16(c, al[mi], bh + nt * 2);
                    }
                }
            }
        }
        __syncthreads();
    }

    const int g  = lane >> 2;
    const int tg = lane & 3;
    #pragma unroll
    for (int mi = 0; mi < 2; mi++) {
        const int row = m0 + warp_m * 32 + mi * 16 + g;
        #pragma unroll
        for (int nt = 0; nt < 8; nt++) {
            const int col = n0 + warp_n * 64 + nt * 8 + tg * 2;
            float2 v0, v1;
            v0.x = acc[mi][nt][0];
            v0.y = acc[mi][nt][1];
            v1.x = acc[mi][nt][2];
            v1.y = acc[mi][nt][3];
            *reinterpret_cast<float2*>(C + (long)row * ldc + col) = v0;
            *reinterpret_cast<float2*>(C + (long)(row + 8) * ldc + col) = v1;
        }
    }
}

// ======================= fused flash attention =============================
// Grid: (SEQ/64, BATCH*HEADS). 128 threads = 4 warps; warp w owns 16 q-rows.
// 2 CTAs/SM (regs ~240 * 128 thr, smem 88KB) -> cross-CTA phase overlap.
#define LDQK 72     // bf16 stride for Q/K tiles (144 B rows)
#define LDVT 136    // bf16 stride for V^T tile (272 B rows)

#define ATT_QH 0
#define ATT_QL 9216
#define ATT_KH 18432
#define ATT_KL 36864
#define ATT_VH 55296
#define ATT_VL 72704
#define ATT_SMEM 90112

__global__ __launch_bounds__(128, 2)
void attn_fused(const float* __restrict__ Q, const float* __restrict__ Kg,
                const float* __restrict__ Vg, float* __restrict__ Og)
{
    extern __shared__ char dsm[];
    const uint32_t sb  = smem_u32_of(dsm);
    const uint32_t sQh = sb + ATT_QH, sQl = sb + ATT_QL;
    const uint32_t sKh = sb + ATT_KH, sKl = sb + ATT_KL;
    const uint32_t sVh = sb + ATT_VH, sVl = sb + ATT_VL;

    const int tid  = threadIdx.x;
    const int wid  = tid >> 5;
    const int lane = tid & 31;
    const int g    = lane >> 2;
    const int tg   = lane & 3;

    const int bh = blockIdx.y;
    const int b  = bh >> 4;
    const int h  = bh & 15;
    const int q0 = blockIdx.x * 64;

    const float* Qp = Q  + ((long)(b * SEQ + q0)) * DMODEL + h * KDIM;
    const float* Kp = Kg + ((long)(b * SEQ)) * DMODEL + h * KDIM;
    const float* Vp = Vg + ((long)(b * SEQ)) * DMODEL + h * KDIM;

    const float SC = 0.125f * 1.4426950408889634f;

    // ---- load Q tile (64 rows x 64 d, scaled, hi/lo split) ----
    {
        const int r = tid >> 1, dseg = (tid & 1) * 32;
        const float* gp = Qp + (long)r * DMODEL + dseg;
        uint32_t hi[16], lo[16];
        #pragma unroll
        for (int i = 0; i < 8; i++) {
            float4 v = *reinterpret_cast<const float4*>(gp + i * 4);
            split2(v.x * SC, v.y * SC, hi[2 * i],     lo[2 * i]);
            split2(v.z * SC, v.w * SC, hi[2 * i + 1], lo[2 * i + 1]);
        }
        const uint32_t ad = (uint32_t)(r * LDQK + dseg) * 2;
        #pragma unroll
        for (int q = 0; q < 4; q++) {
            st128(sQh + ad + q * 16, hi[4 * q], hi[4 * q + 1], hi[4 * q + 2], hi[4 * q + 3]);
            st128(sQl + ad + q * 16, lo[4 * q], lo[4 * q + 1], lo[4 * q + 2], lo[4 * q + 3]);
        }
    }
    __syncthreads();

    // ---- Q fragments in registers for whole kernel ----
    uint32_t qh[4][4], ql[4][4];
    #pragma unroll
    for (int ks = 0; ks < 4; ks++) {
        const int row = wid * 16 + (lane & 15);
        const int col = ks * 16 + (lane >> 4) * 8;
        const uint32_t off = (uint32_t)(row * LDQK + col) * 2;
        ldmatrix_x4(qh[ks], sQh + off);
        ldmatrix_x4(ql[ks], sQl + off);
    }

    float m_run[2] = {-1e30f, -1e30f};
    float l_run[2] = {0.f, 0.f};
    float acc_o[8][4];
    #pragma unroll
    for (int i = 0; i < 8; i++)
        #pragma unroll
        for (int q = 0; q < 4; q++) acc_o[i][q] = 0.f;

    for (int kv = 0; kv < SEQ; kv += 128) {
        // ---- load K tile [128 s][64 d] hi/lo: 1 thread per row, 2 halves of 32 d ----
        {
            const float* gp = Kp + (long)(kv + tid) * DMODEL;
            const uint32_t ad = (uint32_t)(tid * LDQK) * 2;
            #pragma unroll
            for (int half = 0; half < 2; half++) {
                uint32_t hi[16], lo[16];
                #pragma unroll
                for (int i = 0; i < 8; i++) {
                    float4 v = *reinterpret_cast<const float4*>(gp + half * 32 + i * 4);
                    split2(v.x, v.y, hi[2 * i],     lo[2 * i]);
                    split2(v.z, v.w, hi[2 * i + 1], lo[2 * i + 1]);
                }
                const uint32_t a2 = ad + half * 64;
                #pragma unroll
                for (int q = 0; q < 4; q++) {
                    st128(sKh + a2 + q * 16, hi[4 * q], hi[4 * q + 1], hi[4 * q + 2], hi[4 * q + 3]);
                    st128(sKl + a2 + q * 16, lo[4 * q], lo[4 * q + 1], lo[4 * q + 2], lo[4 * q + 3]);
                }
            }
        }
        // ---- load V tile transposed: Vt[d][s], 32B-granule XOR swizzle ----
        {
            const int sp   = tid >> 1;          // s-pair 0..63
            const int dseg = (tid & 1) * 32;
            const float* g0 = Vp + (long)(kv + 2 * sp) * DMODEL + dseg;
            const float* g1 = g0 + DMODEL;
            #pragma unroll
            for (int half = 0; half < 2; half++) {
                float a[16], c[16];
                #pragma unroll
                for (int i = 0; i < 4; i++) {
                    *reinterpret_cast<float4*>(&a[4 * i]) =
                        *reinterpret_cast<const float4*>(g0 + half * 16 + 4 * i);
                    *reinterpret_cast<float4*>(&c[4 * i]) =
                        *reinterpret_cast<const float4*>(g1 + half * 16 + 4 * i);
                }
                #pragma unroll
                for (int j = 0; j < 16; j++) {
                    const int d = dseg + half * 16 + j;
                    uint32_t hi, lo;
                    split2(a[j], c[j], hi, lo);
                    uint32_t off = (uint32_t)(d * LDVT + 2 * sp) * 2;
                    off ^= ((uint32_t)(d >> 4) & 3u) << 5;
                    sts32(sVh + off, hi);
                    sts32(sVl + off, lo);
                }
            }
        }
        __syncthreads();

        // ---- S = Q K^T : per warp 16x128 in 16 n8-tiles ----
        float s_acc[16][4];
        #pragma unroll
        for (int t = 0; t < 16; t++)
            #pragma unroll
            for (int q = 0; q < 4; q++) s_acc[t][q] = 0.f;

        #pragma unroll
        for (int ks = 0; ks < 4; ks++) {
            #pragma unroll
            for (int ng = 0; ng < 8; ng++) {
                const int nrow = ng * 16 + (lane & 7) + ((lane >> 4) << 3);
                const int kcol = ks * 16 + ((lane >> 3) & 1) * 8;
                const uint32_t off = (uint32_t)(nrow * LDQK + kcol) * 2;
                uint32_t bh4[4], bl4[4];
                ldmatrix_x4(bh4, sKh + off);
                ldmatrix_x4(bl4, sKl + off);
                #pragma unroll
                for (int nt = 0; nt < 2; nt++) {
                    float* c = s_acc[ng * 2 + nt];
                    mma_bf16(c, qh[ks], bh4 + nt * 2);
                    mma_bf16(c, qh[ks], bl4 + nt * 2);
                    mma_bf16(c, ql[ks], bh4 + nt * 2);
                }
            }
        }

        // ---- online softmax (base-2) ----
        float mnew0 = m_run[0], mnew1 = m_run[1];
        #pragma unroll
        for (int t = 0; t < 16; t++) {
            mnew0 = fmaxf(mnew0, fmaxf(s_acc[t][0], s_acc[t][1]));
            mnew1 = fmaxf(mnew1, fmaxf(s_acc[t][2], s_acc[t][3]));
        }
        mnew0 = fmaxf(mnew0, __shfl_xor_sync(0xFFFFFFFFu, mnew0, 1));
        mnew0 = fmaxf(mnew0, __shfl_xor_sync(0xFFFFFFFFu, mnew0, 2));
        mnew1 = fmaxf(mnew1, __shfl_xor_sync(0xFFFFFFFFu, mnew1, 1));
        mnew1 = fmaxf(mnew1, __shfl_xor_sync(0xFFFFFFFFu, mnew1, 2));

        const float fac0 = ex2(m_run[0] - mnew0);
        const float fac1 = ex2(m_run[1] - mnew1);
        m_run[0] = mnew0; m_run[1] = mnew1;
        l_run[0] *= fac0; l_run[1] *= fac1;
        #pragma unroll
        for (int i = 0; i < 8; i++) {
            acc_o[i][0] *= fac0; acc_o[i][1] *= fac0;
            acc_o[i][2] *= fac1; acc_o[i][3] *= fac1;
        }

        // ---- P = exp2(S - m); pack into A-fragments (hi/lo) ----
        uint32_t ph[8][4], pl[8][4];
        float rs0 = 0.f, rs1 = 0.f;
        #pragma unroll
        for (int t = 0; t < 16; t++) {
            const float p0 = ex2(s_acc[t][0] - mnew0);
            const float p1 = ex2(s_acc[t][1] - mnew0);
            const float p2 = ex2(s_acc[t][2] - mnew1);
            const float p3 = ex2(s_acc[t][3] - mnew1);
            rs0 += p0 + p1;
            rs1 += p2 + p3;
            const int kk = t >> 1, half = t & 1;
            split2(p0, p1, ph[kk][2 * half],     pl[kk][2 * half]);
            split2(p2, p3, ph[kk][2 * half + 1], pl[kk][2 * half + 1]);
        }
        rs0 += __shfl_xor_sync(0xFFFFFFFFu, rs0, 1);
        rs0 += __shfl_xor_sync(0xFFFFFFFFu, rs0, 2);
        rs1 += __shfl_xor_sync(0xFFFFFFFFu, rs1, 1);
        rs1 += __shfl_xor_sync(0xFFFFFFFFu, rs1, 2);
        l_run[0] += rs0; l_run[1] += rs1;

        // ---- O += P V : k = 128 (8 k-steps), n = 64 (8 n8-tiles) ----
        #pragma unroll
        for (int kk = 0; kk < 8; kk++) {
            #pragma unroll
            for (int ndp = 0; ndp < 4; ndp++) {
                const int nrow = ndp * 16 + (lane & 7) + ((lane >> 4) << 3);
                const int kcol = kk * 16 + ((lane >> 3) & 1) * 8;
                uint32_t off = (uint32_t)(nrow * LDVT + kcol) * 2;
                off ^= ((uint32_t)(nrow >> 4) & 3u) << 5;
                uint32_t vh4[4], vl4[4];
                ldmatrix_x4(vh4, sVh + off);
                ldmatrix_x4(vl4, sVl + off);
                #pragma unroll
                for (int nt = 0; nt < 2; nt++) {
                    float* c = acc_o[ndp * 2 + nt];
                    mma_bf16(c, ph[kk], vh4 + nt * 2);
                    mma_bf16(c, ph[kk], vl4 + nt * 2);
                    mma_bf16(c, pl[kk], vh4 + nt * 2);
                }
            }
        }
        __syncthreads();
    }

    // ---- epilogue ----
    const float inv0 = 1.0f / l_run[0];
    const float inv1 = 1.0f / l_run[1];
    const long row0 = (long)(b * SEQ + q0 + wid * 16 + g);
    #pragma unroll
    for (int nt = 0; nt < 8; nt++) {
        const int col = h * KDIM + nt * 8 + tg * 2;
        float2 v0, v1;
        v0.x = acc_o[nt][0] * inv0;
        v0.y = acc_o[nt][1] * inv0;
        v1.x = acc_o[nt][2] * inv1;
        v1.y = acc_o[nt][3] * inv1;
        *reinterpret_cast<float2*>(Og + row0 * DMODEL + col) = v0;
        *reinterpret_cast<float2*>(Og + (row0 + 8) * DMODEL + col) = v1;
    }
}

// ---------------------------------------------------------------------------
extern "C" void kernel_launch(void* const* d_in, const int* in_sizes, int n_in,
                              void* d_out, int out_size)
{
    const float* X  = (const float*)d_in[0];
    const float* Wq = (const float*)d_in[1];
    const float* Wk = (const float*)d_in[2];
    const float* Wv = (const float*)d_in[3];
    const float* Wo = (const float*)d_in[4];
    float* out = (float*)d_out;

    float *Q, *K, *V, *O;
    cudaGetSymbolAddress((void**)&Q, g_Q);
    cudaGetSymbolAddress((void**)&K, g_K);
    cudaGetSymbolAddress((void**)&V, g_V);
    cudaGetSymbolAddress((void**)&O, g_O);

    cudaFuncSetAttribute(attn_fused,
                         cudaFuncAttributeMaxDynamicSharedMemorySize, ATT_SMEM);

    // --- 1) Projections ---
    {
        dim3 grid(DMODEL / 128, MTOT / 128);
        gemm_mma<<<grid, 256>>>(X, Wq, Q, DMODEL, DMODEL, DMODEL, DMODEL);
        gemm_mma<<<grid, 256>>>(X, Wk, K, DMODEL, DMODEL, DMODEL, DMODEL);
        gemm_mma<<<grid, 256>>>(X, Wv, V, DMODEL, DMODEL, DMODEL, DMODEL);
    }

    // --- 2) Fused attention ---
    {
        dim3 grid(SEQ / 64, BATCH * HEADS);
        attn_fused<<<grid, 128, ATT_SMEM>>>(Q, K, V, O);
    }

    // --- 3) out = O @ Wo^T ---
    {
        dim3 grid(DMODEL / 128, MTOT / 128);
        gemm_mma<<<grid, 256>>>(O, Wo, out, DMODEL, DMODEL, DMODEL, DMODEL);
    }
}

// round 11
// speedup vs baseline: 1.1863x; 1.1863x over previous
#include <cuda_runtime.h>
#include <cuda_bf16.h>
#include <cstdint>

// ---------------------------------------------------------------------------
// MultiHeadAttention: warp-mma bf16x3 projections + fused flash attention
// R11: projections emit pre-split bf16 hi/lo Q/K/V; attention streams K/V via
//      cp.async double buffering; V consumed via ldmatrix.trans (no scatter).
// ---------------------------------------------------------------------------

#define BATCH   2
#define SEQ     2048
#define DMODEL  1024
#define HEADS   16
#define KDIM    64
#define MTOT    (BATCH * SEQ)           // 4096

// Scratch (device globals; allocation-free).
__device__ __nv_bfloat16 g_Qh[MTOT * DMODEL + 256];
__device__ __nv_bfloat16 g_Ql[MTOT * DMODEL + 256];
__device__ __nv_bfloat16 g_Kh[MTOT * DMODEL + 256];
__device__ __nv_bfloat16 g_Kl[MTOT * DMODEL + 256];
__device__ __nv_bfloat16 g_Vh[MTOT * DMODEL + 256];
__device__ __nv_bfloat16 g_Vl[MTOT * DMODEL + 256];
__device__ float g_O[MTOT * DMODEL + 256];

// ======================= helpers ===========================================
__device__ __forceinline__ uint32_t smem_u32_of(const void* p) {
    uint32_t a;
    asm("{ .reg .u64 t; cvta.to.shared.u64 t, %1; cvt.u32.u64 %0, t; }"
        : "=r"(a) : "l"(p));
    return a;
}

__device__ __forceinline__ void ldmatrix_x4(uint32_t* r, uint32_t addr) {
    asm volatile("ldmatrix.sync.aligned.m8n8.x4.shared.b16 {%0,%1,%2,%3}, [%4];"
        : "=r"(r[0]), "=r"(r[1]), "=r"(r[2]), "=r"(r[3]) : "r"(addr));
}
__device__ __forceinline__ void ldmatrix_x4_t(uint32_t* r, uint32_t addr) {
    asm volatile("ldmatrix.sync.aligned.m8n8.x4.trans.shared.b16 {%0,%1,%2,%3}, [%4];"
        : "=r"(r[0]), "=r"(r[1]), "=r"(r[2]), "=r"(r[3]) : "r"(addr));
}

__device__ __forceinline__ void mma_bf16(float* c, const uint32_t* a, const uint32_t* b) {
    asm volatile(
        "mma.sync.aligned.m16n8k16.row.col.f32.bf16.bf16.f32 "
        "{%0,%1,%2,%3}, {%4,%5,%6,%7}, {%8,%9}, {%0,%1,%2,%3};"
        : "+f"(c[0]), "+f"(c[1]), "+f"(c[2]), "+f"(c[3])
        : "r"(a[0]), "r"(a[1]), "r"(a[2]), "r"(a[3]), "r"(b[0]), "r"(b[1]));
}

__device__ __forceinline__ void st128(uint32_t addr, uint32_t a, uint32_t b,
                                      uint32_t c, uint32_t d) {
    asm volatile("st.shared.v4.b32 [%0], {%1,%2,%3,%4};"
                 :: "r"(addr), "r"(a), "r"(b), "r"(c), "r"(d) : "memory");
}

#define CP_ASYNC16(dst, src) \
    asm volatile("cp.async.cg.shared.global [%0], [%1], 16;" \
                 :: "r"(dst), "l"(src) : "memory")
#define CP_COMMIT() asm volatile("cp.async.commit_group;" ::: "memory")
#define CP_WAIT1()  asm volatile("cp.async.wait_group 1;" ::: "memory")
#define CP_WAIT0()  asm volatile("cp.async.wait_group 0;" ::: "memory")

__device__ __forceinline__ float ex2(float x) {
    float r;
    asm("ex2.approx.ftz.f32 %0, %1;" : "=f"(r) : "f"(x));
    return r;
}

__device__ __forceinline__ void split2(float x, float y, uint32_t& hi, uint32_t& lo) {
    __nv_bfloat16 hx = __float2bfloat16(x);
    __nv_bfloat16 hy = __float2bfloat16(y);
    __nv_bfloat162 h; h.x = hx; h.y = hy;
    hi = *reinterpret_cast<uint32_t*>(&h);
    __nv_bfloat162 l = __floats2bfloat162_rn(x - __bfloat162float(hx),
                                             y - __bfloat162float(hy));
    lo = *reinterpret_cast<uint32_t*>(&l);
}

// ======================= warp-MMA GEMM =====================================
// C[m,n] = alpha * sum_k A[m,k] * B[n,k]. Tile 128x128, K-chunk 32, 256 thr.
// SPLIT=1: write hi/lo bf16 arrays (for Q/K/V); SPLIT=0: write fp32 C.
#define LDSR 40

template <int SPLIT>
__global__ __launch_bounds__(256)
void gemm_mma(const float* __restrict__ A, const float* __restrict__ B,
              float* __restrict__ C,
              __nv_bfloat16* __restrict__ Chi, __nv_bfloat16* __restrict__ Clo,
              float alpha, int K, int lda, int ldb, int ldc)
{
    __shared__ __align__(16) uint16_t As_hi[128 * LDSR];
    __shared__ __align__(16) uint16_t As_lo[128 * LDSR];
    __shared__ __align__(16) uint16_t Bs_hi[128 * LDSR];
    __shared__ __align__(16) uint16_t Bs_lo[128 * LDSR];

    const int tid  = threadIdx.x;
    const int wid  = tid >> 5;
    const int lane = tid & 31;
    const int m0   = blockIdx.y * 128;
    const int n0   = blockIdx.x * 128;
    const int warp_m = wid & 3;
    const int warp_n = wid >> 2;

    float acc[2][8][4];
    #pragma unroll
    for (int i = 0; i < 2; i++)
        #pragma unroll
        for (int j = 0; j < 8; j++)
            #pragma unroll
            for (int q = 0; q < 4; q++) acc[i][j][q] = 0.f;

    const uint32_t sAhi = smem_u32_of(As_hi), sAlo = smem_u32_of(As_lo);
    const uint32_t sBhi = smem_u32_of(Bs_hi), sBlo = smem_u32_of(Bs_lo);

    const int r    = tid >> 1;
    const int kseg = (tid & 1) * 16;
    const float* pA = A + (long)(m0 + r) * lda + kseg;
    const float* pB = B + (long)(n0 + r) * ldb + kseg;
    const uint32_t ad = (uint32_t)(r * LDSR + kseg) * 2;

    float4 va[4], vb[4];
    #pragma unroll
    for (int i = 0; i < 4; i++) {
        va[i] = *reinterpret_cast<const float4*>(pA + i * 4);
        vb[i] = *reinterpret_cast<const float4*>(pB + i * 4);
    }

    for (int k0 = 0; k0 < K; k0 += 32) {
        {
            uint32_t hi[8], lo[8];
            #pragma unroll
            for (int i = 0; i < 4; i++) {
                split2(va[i].x, va[i].y, hi[2 * i],     lo[2 * i]);
                split2(va[i].z, va[i].w, hi[2 * i + 1], lo[2 * i + 1]);
            }
            st128(sAhi + ad,      hi[0], hi[1], hi[2], hi[3]);
            st128(sAhi + ad + 16, hi[4], hi[5], hi[6], hi[7]);
            st128(sAlo + ad,      lo[0], lo[1], lo[2], lo[3]);
            st128(sAlo + ad + 16, lo[4], lo[5], lo[6], lo[7]);
            #pragma unroll
            for (int i = 0; i < 4; i++) {
                split2(vb[i].x, vb[i].y, hi[2 * i],     lo[2 * i]);
                split2(vb[i].z, vb[i].w, hi[2 * i + 1], lo[2 * i + 1]);
            }
            st128(sBhi + ad,      hi[0], hi[1], hi[2], hi[3]);
            st128(sBhi + ad + 16, hi[4], hi[5], hi[6], hi[7]);
            st128(sBlo + ad,      lo[0], lo[1], lo[2], lo[3]);
            st128(sBlo + ad + 16, lo[4], lo[5], lo[6], lo[7]);
        }
        __syncthreads();

        if (k0 + 32 < K) {
            pA += 32; pB += 32;
            #pragma unroll
            for (int i = 0; i < 4; i++) {
                va[i] = *reinterpret_cast<const float4*>(pA + i * 4);
                vb[i] = *reinterpret_cast<const float4*>(pB + i * 4);
            }
        }

        #pragma unroll
        for (int ks = 0; ks < 32; ks += 16) {
            uint32_t ah[2][4], al[2][4];
            #pragma unroll
            for (int mi = 0; mi < 2; mi++) {
                const int row = warp_m * 32 + mi * 16 + (lane & 15);
                const int col = ks + (lane >> 4) * 8;
                const uint32_t off = (uint32_t)(row * LDSR + col) * 2;
                ldmatrix_x4(ah[mi], sAhi + off);
                ldmatrix_x4(al[mi], sAlo + off);
            }
            #pragma unroll
            for (int ng = 0; ng < 4; ng++) {
                const int nb   = warp_n * 64 + ng * 16;
                const int nrow = nb + (lane & 7) + ((lane >> 4) << 3);
                const int kcol = ks + ((lane >> 3) & 1) * 8;
                const uint32_t off = (uint32_t)(nrow * LDSR + kcol) * 2;
                uint32_t bh[4], bl[4];
                ldmatrix_x4(bh, sBhi + off);
                ldmatrix_x4(bl, sBlo + off);
                #pragma unroll
                for (int mi = 0; mi < 2; mi++) {
                    #pragma unroll
                    for (int nt = 0; nt < 2; nt++) {
                        float* c = acc[mi][ng * 2 + nt];
                        mma_bf16(c, ah[mi], bh + nt * 2);
                        mma_bf16(c, ah[mi], bl + nt * 2);
                        mma_bf16(c, al[mi], bh + nt * 2);
                    }
                }
            }
        }
        __syncthreads();
    }

    // ---- epilogue ----
    const int g  = lane >> 2;
    const int tg = lane & 3;
    #pragma unroll
    for (int mi = 0; mi < 2; mi++) {
        const int row = m0 + warp_m * 32 + mi * 16 + g;
        #pragma unroll
        for (int nt = 0; nt < 8; nt++) {
            const int col = n0 + warp_n * 64 + nt * 8 + tg * 2;
            if (SPLIT) {
                uint32_t hi, lo;
                split2(acc[mi][nt][0] * alpha, acc[mi][nt][1] * alpha, hi, lo);
                *reinterpret_cast<uint32_t*>(Chi + (long)row * ldc + col) = hi;
                *reinterpret_cast<uint32_t*>(Clo + (long)row * ldc + col) = lo;
                split2(acc[mi][nt][2] * alpha, acc[mi][nt][3] * alpha, hi, lo);
                *reinterpret_cast<uint32_t*>(Chi + (long)(row + 8) * ldc + col) = hi;
                *reinterpret_cast<uint32_t*>(Clo + (long)(row + 8) * ldc + col) = lo;
            } else {
                float2 v0, v1;
                v0.x = acc[mi][nt][0]; v0.y = acc[mi][nt][1];
                v1.x = acc[mi][nt][2]; v1.y = acc[mi][nt][3];
                *reinterpret_cast<float2*>(C + (long)row * ldc + col) = v0;
                *reinterpret_cast<float2*>(C + (long)(row + 8) * ldc + col) = v1;
            }
        }
    }
}

// ======================= fused flash attention =============================
// Grid: (SEQ/128, BATCH*HEADS). 256 threads = 8 warps; warp w owns 16 q-rows.
// K/V streamed via cp.async, 2-stage double buffer. V row-major + ldmatrix.trans.
#define LDKV 72          // bf16 row stride (144 B)
#define TILE_B 18432     // one 128x72 bf16 buffer

#define ATT_QH 0
#define ATT_QL TILE_B
#define ATT_ST 36864     // stage 0 base; stage size 4*TILE_B
#define STG_SZ (4 * TILE_B)
#define ATT_SMEM (ATT_ST + 2 * STG_SZ)   // 184320

__global__ __launch_bounds__(256)
void attn_fused(const __nv_bfloat16* __restrict__ Qh, const __nv_bfloat16* __restrict__ Ql,
                const __nv_bfloat16* __restrict__ Kh, const __nv_bfloat16* __restrict__ Kl,
                const __nv_bfloat16* __restrict__ Vh, const __nv_bfloat16* __restrict__ Vl,
                float* __restrict__ Og)
{
    extern __shared__ char dsm[];
    const uint32_t sb = smem_u32_of(dsm);

    const int tid  = threadIdx.x;
    const int wid  = tid >> 5;
    const int lane = tid & 31;
    const int g    = lane >> 2;
    const int tg   = lane & 3;

    const int bh = blockIdx.y;
    const int b  = bh >> 4;
    const int h  = bh & 15;
    const int q0 = blockIdx.x * 128;

    const long headoff = (long)h * KDIM;
    const __nv_bfloat16* Qhp = Qh + ((long)(b * SEQ + q0)) * DMODEL + headoff;
    const __nv_bfloat16* Qlp = Ql + ((long)(b * SEQ + q0)) * DMODEL + headoff;
    const __nv_bfloat16* Khp = Kh + ((long)(b * SEQ)) * DMODEL + headoff;
    const __nv_bfloat16* Klp = Kl + ((long)(b * SEQ)) * DMODEL + headoff;
    const __nv_bfloat16* Vhp = Vh + ((long)(b * SEQ)) * DMODEL + headoff;
    const __nv_bfloat16* Vlp = Vl + ((long)(b * SEQ)) * DMODEL + headoff;

    const int row = tid >> 1;            // 0..127
    const int cb  = (tid & 1) * 64;      // byte offset within 128B row
    const uint32_t drow = (uint32_t)(row * (LDKV * 2)) + cb;

    // ---- issue Q + stage0 K/V (group 0) ----
    {
        const char* qs_h = (const char*)(Qhp + (long)row * DMODEL) + cb;
        const char* qs_l = (const char*)(Qlp + (long)row * DMODEL) + cb;
        #pragma unroll
        for (int c = 0; c < 4; c++) {
            CP_ASYNC16(sb + ATT_QH + drow + c * 16, qs_h + c * 16);
            CP_ASYNC16(sb + ATT_QL + drow + c * 16, qs_l + c * 16);
        }
        const char* ks_h = (const char*)(Khp + (long)row * DMODEL) + cb;
        const char* ks_l = (const char*)(Klp + (long)row * DMODEL) + cb;
        const char* vs_h = (const char*)(Vhp + (long)row * DMODEL) + cb;
        const char* vs_l = (const char*)(Vlp + (long)row * DMODEL) + cb;
        const uint32_t s0 = sb + ATT_ST;
        #pragma unroll
        for (int c = 0; c < 4; c++) {
            CP_ASYNC16(s0 + 0 * TILE_B + drow + c * 16, ks_h + c * 16);
            CP_ASYNC16(s0 + 1 * TILE_B + drow + c * 16, ks_l + c * 16);
            CP_ASYNC16(s0 + 2 * TILE_B + drow + c * 16, vs_h + c * 16);
            CP_ASYNC16(s0 + 3 * TILE_B + drow + c * 16, vs_l + c * 16);
        }
        CP_COMMIT();
    }

    uint32_t qh[4][4], ql[4][4];
    float m_run[2] = {-1e30f, -1e30f};
    float l_run[2] = {0.f, 0.f};
    float acc_o[8][4];
    #pragma unroll
    for (int i = 0; i < 8; i++)
        #pragma unroll
        for (int q = 0; q < 4; q++) acc_o[i][q] = 0.f;

    const int NT = SEQ / 128;     // 16 tiles

    for (int t = 0; t < NT; t++) {
        // ---- issue next tile into the other stage ----
        if (t + 1 < NT) {
            const long rbase = (long)((t + 1) * 128 + row) * DMODEL;
            const char* ks_h = (const char*)(Khp + rbase) + cb;
            const char* ks_l = (const char*)(Klp + rbase) + cb;
            const char* vs_h = (const char*)(Vhp + rbase) + cb;
            const char* vs_l = (const char*)(Vlp + rbase) + cb;
            const uint32_t s1 = sb + ATT_ST + ((t + 1) & 1) * STG_SZ;
            #pragma unroll
            for (int c = 0; c < 4; c++) {
                CP_ASYNC16(s1 + 0 * TILE_B + drow + c * 16, ks_h + c * 16);
                CP_ASYNC16(s1 + 1 * TILE_B + drow + c * 16, ks_l + c * 16);
                CP_ASYNC16(s1 + 2 * TILE_B + drow + c * 16, vs_h + c * 16);
                CP_ASYNC16(s1 + 3 * TILE_B + drow + c * 16, vs_l + c * 16);
            }
            CP_COMMIT();
            CP_WAIT1();
        } else {
            CP_WAIT0();
        }
        __syncthreads();

        const uint32_t cur = sb + ATT_ST + (t & 1) * STG_SZ;
        const uint32_t sKh = cur, sKl = cur + TILE_B;
        const uint32_t sVh = cur + 2 * TILE_B, sVl = cur + 3 * TILE_B;

        // ---- Q fragments once (after stage-0 data landed) ----
        if (t == 0) {
            #pragma unroll
            for (int ks = 0; ks < 4; ks++) {
                const int qrow = wid * 16 + (lane & 15);
                const int qcol = ks * 16 + (lane >> 4) * 8;
                const uint32_t off = (uint32_t)(qrow * LDKV + qcol) * 2;
                ldmatrix_x4(qh[ks], sb + ATT_QH + off);
                ldmatrix_x4(ql[ks], sb + ATT_QL + off);
            }
        }

        // ---- S = Q K^T : per warp 16x128 in 16 n8-tiles ----
        float s_acc[16][4];
        #pragma unroll
        for (int tt = 0; tt < 16; tt++)
            #pragma unroll
            for (int q = 0; q < 4; q++) s_acc[tt][q] = 0.f;

        #pragma unroll
        for (int ks = 0; ks < 4; ks++) {
            #pragma unroll
            for (int ng = 0; ng < 8; ng++) {
                const int nrow = ng * 16 + (lane & 7) + ((lane >> 4) << 3);
                const int kcol = ks * 16 + ((lane >> 3) & 1) * 8;
                const uint32_t off = (uint32_t)(nrow * LDKV + kcol) * 2;
                uint32_t bh4[4], bl4[4];
                ldmatrix_x4(bh4, sKh + off);
                ldmatrix_x4(bl4, sKl + off);
                #pragma unroll
                for (int nt = 0; nt < 2; nt++) {
                    float* c = s_acc[ng * 2 + nt];
                    mma_bf16(c, qh[ks], bh4 + nt * 2);
                    mma_bf16(c, qh[ks], bl4 + nt * 2);
                    mma_bf16(c, ql[ks], bh4 + nt * 2);
                }
            }
        }

        // ---- online softmax (base-2) ----
        float mnew0 = m_run[0], mnew1 = m_run[1];
        #pragma unroll
        for (int tt = 0; tt < 16; tt++) {
            mnew0 = fmaxf(mnew0, fmaxf(s_acc[tt][0], s_acc[tt][1]));
            mnew1 = fmaxf(mnew1, fmaxf(s_acc[tt][2], s_acc[tt][3]));
        }
        mnew0 = fmaxf(mnew0, __shfl_xor_sync(0xFFFFFFFFu, mnew0, 1));
        mnew0 = fmaxf(mnew0, __shfl_xor_sync(0xFFFFFFFFu, mnew0, 2));
        mnew1 = fmaxf(mnew1, __shfl_xor_sync(0xFFFFFFFFu, mnew1, 1));
        mnew1 = fmaxf(mnew1, __shfl_xor_sync(0xFFFFFFFFu, mnew1, 2));

        const float fac0 = ex2(m_run[0] - mnew0);
        const float fac1 = ex2(m_run[1] - mnew1);
        m_run[0] = mnew0; m_run[1] = mnew1;
        l_run[0] *= fac0; l_run[1] *= fac1;
        #pragma unroll
        for (int i = 0; i < 8; i++) {
            acc_o[i][0] *= fac0; acc_o[i][1] *= fac0;
            acc_o[i][2] *= fac1; acc_o[i][3] *= fac1;
        }

        // ---- P = exp2(S - m); pack into A-fragments (hi/lo) ----
        uint32_t ph[8][4], pl[8][4];
        float rs0 = 0.f, rs1 = 0.f;
        #pragma unroll
        for (int tt = 0; tt < 16; tt++) {
            const float p0 = ex2(s_acc[tt][0] - mnew0);
            const float p1 = ex2(s_acc[tt][1] - mnew0);
            const float p2 = ex2(s_acc[tt][2] - mnew1);
            const float p3 = ex2(s_acc[tt][3] - mnew1);
            rs0 += p0 + p1;
            rs1 += p2 + p3;
            const int kk = tt >> 1, half = tt & 1;
            split2(p0, p1, ph[kk][2 * half],     pl[kk][2 * half]);
            split2(p2, p3, ph[kk][2 * half + 1], pl[kk][2 * half + 1]);
        }
        rs0 += __shfl_xor_sync(0xFFFFFFFFu, rs0, 1);
        rs0 += __shfl_xor_sync(0xFFFFFFFFu, rs0, 2);
        rs1 += __shfl_xor_sync(0xFFFFFFFFu, rs1, 1);
        rs1 += __shfl_xor_sync(0xFFFFFFFFu, rs1, 2);
        l_run[0] += rs0; l_run[1] += rs1;

        // ---- O += P V : V [s][d] row-major, B-frags via ldmatrix.trans ----
        #pragma unroll
        for (int kk = 0; kk < 8; kk++) {
            #pragma unroll
            for (int ndp = 0; ndp < 4; ndp++) {
                const int krow = kk * 16 + ((lane >> 3) & 1) * 8 + (lane & 7);
                const int ncol = ndp * 16 + ((lane >> 4) << 3);
                const uint32_t off = (uint32_t)(krow * LDKV + ncol) * 2;
                uint32_t vh4[4], vl4[4];
                ldmatrix_x4_t(vh4, sVh + off);
                ldmatrix_x4_t(vl4, sVl + off);
                #pragma unroll
                for (int nt = 0; nt < 2; nt++) {
                    float* c = acc_o[ndp * 2 + nt];
                    mma_bf16(c, ph[kk], vh4 + nt * 2);
                    mma_bf16(c, ph[kk], vl4 + nt * 2);
                    mma_bf16(c, pl[kk], vh4 + nt * 2);
                }
            }
        }
        __syncthreads();
    }

    // ---- epilogue: O /= l, write [s][h*64+d] ----
    const float inv0 = 1.0f / l_run[0];
    const float inv1 = 1.0f / l_run[1];
    const long row0 = (long)(b * SEQ + q0 + wid * 16 + g);
    #pragma unroll
    for (int nt = 0; nt < 8; nt++) {
        const int col = h * KDIM + nt * 8 + tg * 2;
        float2 v0, v1;
        v0.x = acc_o[nt][0] * inv0;
        v0.y = acc_o[nt][1] * inv0;
        v1.x = acc_o[nt][2] * inv1;
        v1.y = acc_o[nt][3] * inv1;
        *reinterpret_cast<float2*>(Og + row0 * DMODEL + col) = v0;
        *reinterpret_cast<float2*>(Og + (row0 + 8) * DMODEL + col) = v1;
    }
}

// ---------------------------------------------------------------------------
extern "C" void kernel_launch(void* const* d_in, const int* in_sizes, int n_in,
                              void* d_out, int out_size)
{
    const float* X  = (const float*)d_in[0];
    const float* Wq = (const float*)d_in[1];
    const float* Wk = (const float*)d_in[2];
    const float* Wv = (const float*)d_in[3];
    const float* Wo = (const float*)d_in[4];
    float* out = (float*)d_out;

    __nv_bfloat16 *Qh, *Ql, *Kh, *Kl, *Vh, *Vl;
    float *O;
    cudaGetSymbolAddress((void**)&Qh, g_Qh);
    cudaGetSymbolAddress((void**)&Ql, g_Ql);
    cudaGetSymbolAddress((void**)&Kh, g_Kh);
    cudaGetSymbolAddress((void**)&Kl, g_Kl);
    cudaGetSymbolAddress((void**)&Vh, g_Vh);
    cudaGetSymbolAddress((void**)&Vl, g_Vl);
    cudaGetSymbolAddress((void**)&O,  g_O);

    cudaFuncSetAttribute(attn_fused,
                         cudaFuncAttributeMaxDynamicSharedMemorySize, ATT_SMEM);

    const float SC = 0.125f * 1.4426950408889634f;

    // --- 1) Projections (emit pre-split bf16; Q pre-scaled) ---
    {
        dim3 grid(DMODEL / 128, MTOT / 128);
        gemm_mma<1><<<grid, 256>>>(X, Wq, nullptr, Qh, Ql, SC,
                                   DMODEL, DMODEL, DMODEL, DMODEL);
        gemm_mma<1><<<grid, 256>>>(X, Wk, nullptr, Kh, Kl, 1.0f,
                                   DMODEL, DMODEL, DMODEL, DMODEL);
        gemm_mma<1><<<grid, 256>>>(X, Wv, nullptr, Vh, Vl, 1.0f,
                                   DMODEL, DMODEL, DMODEL, DMODEL);
    }

    // --- 2) Fused attention ---
    {
        dim3 grid(SEQ / 128, BATCH * HEADS);
        attn_fused<<<grid, 256, ATT_SMEM>>>(Qh, Ql, Kh, Kl, Vh, Vl, O);
    }

    // --- 3) out = O @ Wo^T ---
    {
        dim3 grid(DMODEL / 128, MTOT / 128);
        gemm_mma<0><<<grid, 256>>>(O, Wo, out, nullptr, nullptr, 1.0f,
                                   DMODEL, DMODEL, DMODEL, DMODEL);
    }
}

// round 13
// speedup vs baseline: 1.2466x; 1.0508x over previous
#include <cuda_runtime.h>
#include <cuda_bf16.h>
#include <cstdint>

// ---------------------------------------------------------------------------
// MultiHeadAttention R13:
//  - pre-pass splits X and W into bf16 hi/lo once
//  - pure-bf16 cp.async double-buffered GEMM (no in-loop conversion), 2 CTA/SM
//  - fused flash attention (cp.async K/V), PV bf16x3 (P hi/lo restored),
//    O written pre-split
// ---------------------------------------------------------------------------

#define BATCH   2
#define SEQ     2048
#define DMODEL  1024
#define HEADS   16
#define KDIM    64
#define MTOT    (BATCH * SEQ)           // 4096

// Scratch (device globals; allocation-free).
__device__ __nv_bfloat16 g_Xh[MTOT * DMODEL + 256];
__device__ __nv_bfloat16 g_Xl[MTOT * DMODEL + 256];
__device__ __nv_bfloat16 g_Wh[4 * DMODEL * DMODEL + 256];   // q,k,v,o
__device__ __nv_bfloat16 g_Wl[4 * DMODEL * DMODEL + 256];
__device__ __nv_bfloat16 g_Qh[MTOT * DMODEL + 256];
__device__ __nv_bfloat16 g_Ql[MTOT * DMODEL + 256];
__device__ __nv_bfloat16 g_Kh[MTOT * DMODEL + 256];
__device__ __nv_bfloat16 g_Kl[MTOT * DMODEL + 256];
__device__ __nv_bfloat16 g_Vh[MTOT * DMODEL + 256];
__device__ __nv_bfloat16 g_Vl[MTOT * DMODEL + 256];
__device__ __nv_bfloat16 g_Oh[MTOT * DMODEL + 256];
__device__ __nv_bfloat16 g_Ol[MTOT * DMODEL + 256];

// ======================= helpers ===========================================
__device__ __forceinline__ uint32_t smem_u32_of(const void* p) {
    uint32_t a;
    asm("{ .reg .u64 t; cvta.to.shared.u64 t, %1; cvt.u32.u64 %0, t; }"
        : "=r"(a) : "l"(p));
    return a;
}

__device__ __forceinline__ void ldmatrix_x4(uint32_t* r, uint32_t addr) {
    asm volatile("ldmatrix.sync.aligned.m8n8.x4.shared.b16 {%0,%1,%2,%3}, [%4];"
        : "=r"(r[0]), "=r"(r[1]), "=r"(r[2]), "=r"(r[3]) : "r"(addr));
}
__device__ __forceinline__ void ldmatrix_x4_t(uint32_t* r, uint32_t addr) {
    asm volatile("ldmatrix.sync.aligned.m8n8.x4.trans.shared.b16 {%0,%1,%2,%3}, [%4];"
        : "=r"(r[0]), "=r"(r[1]), "=r"(r[2]), "=r"(r[3]) : "r"(addr));
}

__device__ __forceinline__ void mma_bf16(float* c, const uint32_t* a, const uint32_t* b) {
    asm volatile(
        "mma.sync.aligned.m16n8k16.row.col.f32.bf16.bf16.f32 "
        "{%0,%1,%2,%3}, {%4,%5,%6,%7}, {%8,%9}, {%0,%1,%2,%3};"
        : "+f"(c[0]), "+f"(c[1]), "+f"(c[2]), "+f"(c[3])
        : "r"(a[0]), "r"(a[1]), "r"(a[2]), "r"(a[3]), "r"(b[0]), "r"(b[1]));
}

#define CP_ASYNC16(dst, src) \
    asm volatile("cp.async.cg.shared.global [%0], [%1], 16;" \
                 :: "r"(dst), "l"(src) : "memory")
#define CP_COMMIT() asm volatile("cp.async.commit_group;" ::: "memory")
#define CP_WAIT1()  asm volatile("cp.async.wait_group 1;" ::: "memory")
#define CP_WAIT0()  asm volatile("cp.async.wait_group 0;" ::: "memory")

__device__ __forceinline__ float ex2(float x) {
    float r;
    asm("ex2.approx.ftz.f32 %0, %1;" : "=f"(r) : "f"(x));
    return r;
}

__device__ __forceinline__ void split2(float x, float y, uint32_t& hi, uint32_t& lo) {
    __nv_bfloat16 hx = __float2bfloat16(x);
    __nv_bfloat16 hy = __float2bfloat16(y);
    __nv_bfloat162 h; h.x = hx; h.y = hy;
    hi = *reinterpret_cast<uint32_t*>(&h);
    __nv_bfloat162 l = __floats2bfloat162_rn(x - __bfloat162float(hx),
                                             y - __bfloat162float(hy));
    lo = *reinterpret_cast<uint32_t*>(&l);
}

// ======================= pre-pass: fp32 -> bf16 hi/lo ======================
__global__ __launch_bounds__(256)
void conv_split(const float* __restrict__ s,
                __nv_bfloat16* __restrict__ h, __nv_bfloat16* __restrict__ l,
                int n4)
{
    const int i = blockIdx.x * blockDim.x + threadIdx.x;
    if (i < n4) {
        float4 v = reinterpret_cast<const float4*>(s)[i];
        uint32_t h0, l0, h1, l1;
        split2(v.x, v.y, h0, l0);
        split2(v.z, v.w, h1, l1);
        uint2 hh; hh.x = h0; hh.y = h1;
        uint2 ll; ll.x = l0; ll.y = l1;
        reinterpret_cast<uint2*>(h)[i] = hh;
        reinterpret_cast<uint2*>(l)[i] = ll;
    }
}

// ======================= pure-bf16 warp-MMA GEMM ===========================
// C[m,n] = alpha * sum_k A[m,k]*B[n,k] with A,B given as bf16 hi/lo pairs.
// Tile 128x128, K-chunk 32, 256 thr (4x2 warps), cp.async 2-stage.
#define LDSR 40                     // bf16 row stride (80 B)
#define GBUF 10240                  // 128 * 80 B, one operand buffer
#define GSTG (4 * GBUF)             // Ah, Al, Bh, Bl
#define GSMEM (2 * GSTG)            // 81920 B

template <int SPLIT>
__global__ __launch_bounds__(256, 2)
void gemm_bf3(const __nv_bfloat16* __restrict__ Ah, const __nv_bfloat16* __restrict__ Al,
              const __nv_bfloat16* __restrict__ Bh, const __nv_bfloat16* __restrict__ Bl,
              float* __restrict__ C,
              __nv_bfloat16* __restrict__ Chi, __nv_bfloat16* __restrict__ Clo,
              float alpha, int K, int lda, int ldb, int ldc)
{
    extern __shared__ char dsm[];
    const uint32_t sb = smem_u32_of(dsm);

    const int tid  = threadIdx.x;
    const int wid  = tid >> 5;
    const int lane = tid & 31;
    const int m0   = blockIdx.y * 128;
    const int n0   = blockIdx.x * 128;
    const int warp_m = wid & 3;
    const int warp_n = wid >> 2;

    float acc[2][8][4];
    #pragma unroll
    for (int i = 0; i < 2; i++)
        #pragma unroll
        for (int j = 0; j < 8; j++)
            #pragma unroll
            for (int q = 0; q < 4; q++) acc[i][j][q] = 0.f;

    const int r  = tid >> 1;
    const int cb = (tid & 1) * 32;            // byte offset in 64 B row
    const uint32_t drow = (uint32_t)(r * 80) + cb;
    const char* pAh = (const char*)(Ah + (long)(m0 + r) * lda) + cb;
    const char* pAl = (const char*)(Al + (long)(m0 + r) * lda) + cb;
    const char* pBh = (const char*)(Bh + (long)(n0 + r) * ldb) + cb;
    const char* pBl = (const char*)(Bl + (long)(n0 + r) * ldb) + cb;

    const int NC = K / 32;

    // issue chunk 0
    {
        const uint32_t s0 = sb;
        CP_ASYNC16(s0 + 0 * GBUF + drow,      pAh);
        CP_ASYNC16(s0 + 0 * GBUF + drow + 16, pAh + 16);
        CP_ASYNC16(s0 + 1 * GBUF + drow,      pAl);
        CP_ASYNC16(s0 + 1 * GBUF + drow + 16, pAl + 16);
        CP_ASYNC16(s0 + 2 * GBUF + drow,      pBh);
        CP_ASYNC16(s0 + 2 * GBUF + drow + 16, pBh + 16);
        CP_ASYNC16(s0 + 3 * GBUF + drow,      pBl);
        CP_ASYNC16(s0 + 3 * GBUF + drow + 16, pBl + 16);
        CP_COMMIT();
    }

    for (int c = 0; c < NC; c++) {
        if (c + 1 < NC) {
            const uint32_t s1 = sb + ((c + 1) & 1) * GSTG;
            const long go = (long)(c + 1) * 64;
            CP_ASYNC16(s1 + 0 * GBUF + drow,      pAh + go);
            CP_ASYNC16(s1 + 0 * GBUF + drow + 16, pAh + go + 16);
            CP_ASYNC16(s1 + 1 * GBUF + drow,      pAl + go);
            CP_ASYNC16(s1 + 1 * GBUF + drow + 16, pAl + go + 16);
            CP_ASYNC16(s1 + 2 * GBUF + drow,      pBh + go);
            CP_ASYNC16(s1 + 2 * GBUF + drow + 16, pBh + go + 16);
            CP_ASYNC16(s1 + 3 * GBUF + drow,      pBl + go);
            CP_ASYNC16(s1 + 3 * GBUF + drow + 16, pBl + go + 16);
            CP_COMMIT();
            CP_WAIT1();
        } else {
            CP_WAIT0();
        }
        __syncthreads();

        const uint32_t cur = sb + (c & 1) * GSTG;
        const uint32_t sAhi = cur, sAlo = cur + GBUF;
        const uint32_t sBhi = cur + 2 * GBUF, sBlo = cur + 3 * GBUF;

        #pragma unroll
        for (int ks = 0; ks < 32; ks += 16) {
            uint32_t ah[2][4], al[2][4];
            #pragma unroll
            for (int mi = 0; mi < 2; mi++) {
                const int row = warp_m * 32 + mi * 16 + (lane & 15);
                const int col = ks + (lane >> 4) * 8;
                const uint32_t off = (uint32_t)(row * LDSR + col) * 2;
                ldmatrix_x4(ah[mi], sAhi + off);
                ldmatrix_x4(al[mi], sAlo + off);
            }
            #pragma unroll
            for (int ng = 0; ng < 4; ng++) {
                const int nb   = warp_n * 64 + ng * 16;
                const int nrow = nb + (lane & 7) + ((lane >> 4) << 3);
                const int kcol = ks + ((lane >> 3) & 1) * 8;
                const uint32_t off = (uint32_t)(nrow * LDSR + kcol) * 2;
                uint32_t bh[4], bl[4];
                ldmatrix_x4(bh, sBhi + off);
                ldmatrix_x4(bl, sBlo + off);
                #pragma unroll
                for (int mi = 0; mi < 2; mi++) {
                    #pragma unroll
                    for (int nt = 0; nt < 2; nt++) {
                        float* cc = acc[mi][ng * 2 + nt];
                        mma_bf16(cc, ah[mi], bh + nt * 2);
                        mma_bf16(cc, ah[mi], bl + nt * 2);
                        mma_bf16(cc, al[mi], bh + nt * 2);
                    }
                }
            }
        }
        __syncthreads();
    }

    // ---- epilogue ----
    const int g  = lane >> 2;
    const int tg = lane & 3;
    #pragma unroll
    for (int mi = 0; mi < 2; mi++) {
        const int row = m0 + warp_m * 32 + mi * 16 + g;
        #pragma unroll
        for (int nt = 0; nt < 8; nt++) {
            const int col = n0 + warp_n * 64 + nt * 8 + tg * 2;
            if (SPLIT) {
                uint32_t hi, lo;
                split2(acc[mi][nt][0] * alpha, acc[mi][nt][1] * alpha, hi, lo);
                *reinterpret_cast<uint32_t*>(Chi + (long)row * ldc + col) = hi;
                *reinterpret_cast<uint32_t*>(Clo + (long)row * ldc + col) = lo;
                split2(acc[mi][nt][2] * alpha, acc[mi][nt][3] * alpha, hi, lo);
                *reinterpret_cast<uint32_t*>(Chi + (long)(row + 8) * ldc + col) = hi;
                *reinterpret_cast<uint32_t*>(Clo + (long)(row + 8) * ldc + col) = lo;
            } else {
                float2 v0, v1;
                v0.x = acc[mi][nt][0]; v0.y = acc[mi][nt][1];
                v1.x = acc[mi][nt][2]; v1.y = acc[mi][nt][3];
                *reinterpret_cast<float2*>(C + (long)row * ldc + col) = v0;
                *reinterpret_cast<float2*>(C + (long)(row + 8) * ldc + col) = v1;
            }
        }
    }
}

// ======================= fused flash attention =============================
// Grid: (SEQ/128, BATCH*HEADS). 256 threads = 8 warps; warp w owns 16 q-rows.
// K/V streamed via cp.async double buffer. PV bf16x3 (P hi/lo).
#define LDKV 72          // bf16 row stride (144 B)
#define TILE_B 18432     // one 128x72 bf16 buffer

#define ATT_QH 0
#define ATT_QL TILE_B
#define ATT_ST 36864
#define STG_SZ (4 * TILE_B)
#define ATT_SMEM (ATT_ST + 2 * STG_SZ)   // 184320

__global__ __launch_bounds__(256)
void attn_fused(const __nv_bfloat16* __restrict__ Qh, const __nv_bfloat16* __restrict__ Ql,
                const __nv_bfloat16* __restrict__ Kh, const __nv_bfloat16* __restrict__ Kl,
                const __nv_bfloat16* __restrict__ Vh, const __nv_bfloat16* __restrict__ Vl,
                __nv_bfloat16* __restrict__ Oh, __nv_bfloat16* __restrict__ Ol)
{
    extern __shared__ char dsm[];
    const uint32_t sb = smem_u32_of(dsm);

    const int tid  = threadIdx.x;
    const int wid  = tid >> 5;
    const int lane = tid & 31;
    const int g    = lane >> 2;
    const int tg   = lane & 3;

    const int bh = blockIdx.y;
    const int b  = bh >> 4;
    const int h  = bh & 15;
    const int q0 = blockIdx.x * 128;

    const long headoff = (long)h * KDIM;
    const __nv_bfloat16* Qhp = Qh + ((long)(b * SEQ + q0)) * DMODEL + headoff;
    const __nv_bfloat16* Qlp = Ql + ((long)(b * SEQ + q0)) * DMODEL + headoff;
    const __nv_bfloat16* Khp = Kh + ((long)(b * SEQ)) * DMODEL + headoff;
    const __nv_bfloat16* Klp = Kl + ((long)(b * SEQ)) * DMODEL + headoff;
    const __nv_bfloat16* Vhp = Vh + ((long)(b * SEQ)) * DMODEL + headoff;
    const __nv_bfloat16* Vlp = Vl + ((long)(b * SEQ)) * DMODEL + headoff;

    const int row = tid >> 1;
    const int cb  = (tid & 1) * 64;
    const uint32_t drow = (uint32_t)(row * (LDKV * 2)) + cb;

    // ---- issue Q + stage0 K/V ----
    {
        const char* qs_h = (const char*)(Qhp + (long)row * DMODEL) + cb;
        const char* qs_l = (const char*)(Qlp + (long)row * DMODEL) + cb;
        #pragma unroll
        for (int c = 0; c < 4; c++) {
            CP_ASYNC16(sb + ATT_QH + drow + c * 16, qs_h + c * 16);
            CP_ASYNC16(sb + ATT_QL + drow + c * 16, qs_l + c * 16);
        }
        const char* ks_h = (const char*)(Khp + (long)row * DMODEL) + cb;
        const char* ks_l = (const char*)(Klp + (long)row * DMODEL) + cb;
        const char* vs_h = (const char*)(Vhp + (long)row * DMODEL) + cb;
        const char* vs_l = (const char*)(Vlp + (long)row * DMODEL) + cb;
        const uint32_t s0 = sb + ATT_ST;
        #pragma unroll
        for (int c = 0; c < 4; c++) {
            CP_ASYNC16(s0 + 0 * TILE_B + drow + c * 16, ks_h + c * 16);
            CP_ASYNC16(s0 + 1 * TILE_B + drow + c * 16, ks_l + c * 16);
            CP_ASYNC16(s0 + 2 * TILE_B + drow + c * 16, vs_h + c * 16);
            CP_ASYNC16(s0 + 3 * TILE_B + drow + c * 16, vs_l + c * 16);
        }
        CP_COMMIT();
    }

    uint32_t qh[4][4], ql[4][4];
    float m_run[2] = {-1e30f, -1e30f};
    float l_run[2] = {0.f, 0.f};
    float acc_o[8][4];
    #pragma unroll
    for (int i = 0; i < 8; i++)
        #pragma unroll
        for (int q = 0; q < 4; q++) acc_o[i][q] = 0.f;

    const int NT = SEQ / 128;

    for (int t = 0; t < NT; t++) {
        if (t + 1 < NT) {
            const long rbase = (long)((t + 1) * 128 + row) * DMODEL;
            const char* ks_h = (const char*)(Khp + rbase) + cb;
            const char* ks_l = (const char*)(Klp + rbase) + cb;
            const char* vs_h = (const char*)(Vhp + rbase) + cb;
            const char* vs_l = (const char*)(Vlp + rbase) + cb;
            const uint32_t s1 = sb + ATT_ST + ((t + 1) & 1) * STG_SZ;
            #pragma unroll
            for (int c = 0; c < 4; c++) {
                CP_ASYNC16(s1 + 0 * TILE_B + drow + c * 16, ks_h + c * 16);
                CP_ASYNC16(s1 + 1 * TILE_B + drow + c * 16, ks_l + c * 16);
                CP_ASYNC16(s1 + 2 * TILE_B + drow + c * 16, vs_h + c * 16);
                CP_ASYNC16(s1 + 3 * TILE_B + drow + c * 16, vs_l + c * 16);
            }
            CP_COMMIT();
            CP_WAIT1();
        } else {
            CP_WAIT0();
        }
        __syncthreads();

        const uint32_t cur = sb + ATT_ST + (t & 1) * STG_SZ;
        const uint32_t sKh = cur, sKl = cur + TILE_B;
        const uint32_t sVh = cur + 2 * TILE_B, sVl = cur + 3 * TILE_B;

        if (t == 0) {
            #pragma unroll
            for (int ks = 0; ks < 4; ks++) {
                const int qrow = wid * 16 + (lane & 15);
                const int qcol = ks * 16 + (lane >> 4) * 8;
                const uint32_t off = (uint32_t)(qrow * LDKV + qcol) * 2;
                ldmatrix_x4(qh[ks], sb + ATT_QH + off);
                ldmatrix_x4(ql[ks], sb + ATT_QL + off);
            }
        }

        // ---- S = Q K^T (bf16x3) ----
        float s_acc[16][4];
        #pragma unroll
        for (int tt = 0; tt < 16; tt++)
            #pragma unroll
            for (int q = 0; q < 4; q++) s_acc[tt][q] = 0.f;

        #pragma unroll
        for (int ks = 0; ks < 4; ks++) {
            #pragma unroll
            for (int ng = 0; ng < 8; ng++) {
                const int nrow = ng * 16 + (lane & 7) + ((lane >> 4) << 3);
                const int kcol = ks * 16 + ((lane >> 3) & 1) * 8;
                const uint32_t off = (uint32_t)(nrow * LDKV + kcol) * 2;
                uint32_t bh4[4], bl4[4];
                ldmatrix_x4(bh4, sKh + off);
                ldmatrix_x4(bl4, sKl + off);
                #pragma unroll
                for (int nt = 0; nt < 2; nt++) {
                    float* c = s_acc[ng * 2 + nt];
                    mma_bf16(c, qh[ks], bh4 + nt * 2);
                    mma_bf16(c, qh[ks], bl4 + nt * 2);
                    mma_bf16(c, ql[ks], bh4 + nt * 2);
                }
            }
        }

        // ---- online softmax (base-2) ----
        float mnew0 = m_run[0], mnew1 = m_run[1];
        #pragma unroll
        for (int tt = 0; tt < 16; tt++) {
            mnew0 = fmaxf(mnew0, fmaxf(s_acc[tt][0], s_acc[tt][1]));
            mnew1 = fmaxf(mnew1, fmaxf(s_acc[tt][2], s_acc[tt][3]));
        }
        mnew0 = fmaxf(mnew0, __shfl_xor_sync(0xFFFFFFFFu, mnew0, 1));
        mnew0 = fmaxf(mnew0, __shfl_xor_sync(0xFFFFFFFFu, mnew0, 2));
        mnew1 = fmaxf(mnew1, __shfl_xor_sync(0xFFFFFFFFu, mnew1, 1));
        mnew1 = fmaxf(mnew1, __shfl_xor_sync(0xFFFFFFFFu, mnew1, 2));

        const float fac0 = ex2(m_run[0] - mnew0);
        const float fac1 = ex2(m_run[1] - mnew1);
        m_run[0] = mnew0; m_run[1] = mnew1;
        l_run[0] *= fac0; l_run[1] *= fac1;
        #pragma unroll
        for (int i = 0; i < 8; i++) {
            acc_o[i][0] *= fac0; acc_o[i][1] *= fac0;
            acc_o[i][2] *= fac1; acc_o[i][3] *= fac1;
        }

        // ---- P = exp2(S - m); pack into A-fragments (hi/lo) ----
        uint32_t ph[8][4], pl[8][4];
        float rs0 = 0.f, rs1 = 0.f;
        #pragma unroll
        for (int tt = 0; tt < 16; tt++) {
            const float p0 = ex2(s_acc[tt][0] - mnew0);
            const float p1 = ex2(s_acc[tt][1] - mnew0);
            const float p2 = ex2(s_acc[tt][2] - mnew1);
            const float p3 = ex2(s_acc[tt][3] - mnew1);
            rs0 += p0 + p1;
            rs1 += p2 + p3;
            const int kk = tt >> 1, half = tt & 1;
            split2(p0, p1, ph[kk][2 * half],     pl[kk][2 * half]);
            split2(p2, p3, ph[kk][2 * half + 1], pl[kk][2 * half + 1]);
        }
        rs0 += __shfl_xor_sync(0xFFFFFFFFu, rs0, 1);
        rs0 += __shfl_xor_sync(0xFFFFFFFFu, rs0, 2);
        rs1 += __shfl_xor_sync(0xFFFFFFFFu, rs1, 1);
        rs1 += __shfl_xor_sync(0xFFFFFFFFu, rs1, 2);
        l_run[0] += rs0; l_run[1] += rs1;

        // ---- O += P V (bf16x3: ph*vh + ph*vl + pl*vh) ----
        #pragma unroll
        for (int kk = 0; kk < 8; kk++) {
            #pragma unroll
            for (int ndp = 0; ndp < 4; ndp++) {
                const int krow = kk * 16 + ((lane >> 3) & 1) * 8 + (lane & 7);
                const int ncol = ndp * 16 + ((lane >> 4) << 3);
                const uint32_t off = (uint32_t)(krow * LDKV + ncol) * 2;
                uint32_t vh4[4], vl4[4];
                ldmatrix_x4_t(vh4, sVh + off);
                ldmatrix_x4_t(vl4, sVl + off);
                #pragma unroll
                for (int nt = 0; nt < 2; nt++) {
                    float* c = acc_o[ndp * 2 + nt];
                    mma_bf16(c, ph[kk], vh4 + nt * 2);
                    mma_bf16(c, ph[kk], vl4 + nt * 2);
                    mma_bf16(c, pl[kk], vh4 + nt * 2);
                }
            }
        }
        __syncthreads();
    }

    // ---- epilogue: O /= l, write pre-split bf16 hi/lo ----
    const float inv0 = 1.0f / l_run[0];
    const float inv1 = 1.0f / l_run[1];
    const long row0 = (long)(b * SEQ + q0 + wid * 16 + g);
    #pragma unroll
    for (int nt = 0; nt < 8; nt++) {
        const int col = h * KDIM + nt * 8 + tg * 2;
        uint32_t hi, lo;
        split2(acc_o[nt][0] * inv0, acc_o[nt][1] * inv0, hi, lo);
        *reinterpret_cast<uint32_t*>(Oh + row0 * DMODEL + col) = hi;
        *reinterpret_cast<uint32_t*>(Ol + row0 * DMODEL + col) = lo;
        split2(acc_o[nt][2] * inv1, acc_o[nt][3] * inv1, hi, lo);
        *reinterpret_cast<uint32_t*>(Oh + (row0 + 8) * DMODEL + col) = hi;
        *reinterpret_cast<uint32_t*>(Ol + (row0 + 8) * DMODEL + col) = lo;
    }
}

// ---------------------------------------------------------------------------
extern "C" void kernel_launch(void* const* d_in, const int* in_sizes, int n_in,
                              void* d_out, int out_size)
{
    const float* X  = (const float*)d_in[0];
    const float* Wq = (const float*)d_in[1];
    const float* Wk = (const float*)d_in[2];
    const float* Wv = (const float*)d_in[3];
    const float* Wo = (const float*)d_in[4];
    float* out = (float*)d_out;

    __nv_bfloat16 *Xh, *Xl, *Wh, *Wl, *Qh, *Ql, *Kh, *Kl, *Vh, *Vl, *Oh, *Ol;
    cudaGetSymbolAddress((void**)&Xh, g_Xh);
    cudaGetSymbolAddress((void**)&Xl, g_Xl);
    cudaGetSymbolAddress((void**)&Wh, g_Wh);
    cudaGetSymbolAddress((void**)&Wl, g_Wl);
    cudaGetSymbolAddress((void**)&Qh, g_Qh);
    cudaGetSymbolAddress((void**)&Ql, g_Ql);
    cudaGetSymbolAddress((void**)&Kh, g_Kh);
    cudaGetSymbolAddress((void**)&Kl, g_Kl);
    cudaGetSymbolAddress((void**)&Vh, g_Vh);
    cudaGetSymbolAddress((void**)&Vl, g_Vl);
    cudaGetSymbolAddress((void**)&Oh, g_Oh);
    cudaGetSymbolAddress((void**)&Ol, g_Ol);

    cudaFuncSetAttribute(attn_fused,
                         cudaFuncAttributeMaxDynamicSharedMemorySize, ATT_SMEM);
    cudaFuncSetAttribute(gemm_bf3<0>,
                         cudaFuncAttributeMaxDynamicSharedMemorySize, GSMEM);
    cudaFuncSetAttribute(gemm_bf3<1>,
                         cudaFuncAttributeMaxDynamicSharedMemorySize, GSMEM);

    const float SC = 0.125f * 1.4426950408889634f;
    const int WSZ = DMODEL * DMODEL;

    // --- 0) pre-split X and weights ---
    {
        const int n4x = MTOT * DMODEL / 4;
        conv_split<<<n4x / 256, 256>>>(X, Xh, Xl, n4x);
        const int n4w = WSZ / 4;
        conv_split<<<n4w / 256, 256>>>(Wq, Wh + 0L * WSZ, Wl + 0L * WSZ, n4w);
        conv_split<<<n4w / 256, 256>>>(Wk, Wh + 1L * WSZ, Wl + 1L * WSZ, n4w);
        conv_split<<<n4w / 256, 256>>>(Wv, Wh + 2L * WSZ, Wl + 2L * WSZ, n4w);
        conv_split<<<n4w / 256, 256>>>(Wo, Wh + 3L * WSZ, Wl + 3L * WSZ, n4w);
    }

    // --- 1) Projections (pure bf16; Q pre-scaled) ---
    {
        dim3 grid(DMODEL / 128, MTOT / 128);
        gemm_bf3<1><<<grid, 256, GSMEM>>>(Xh, Xl, Wh + 0L * WSZ, Wl + 0L * WSZ,
            nullptr, Qh, Ql, SC, DMODEL, DMODEL, DMODEL, DMODEL);
        gemm_bf3<1><<<grid, 256, GSMEM>>>(Xh, Xl, Wh + 1L * WSZ, Wl + 1L * WSZ,
            nullptr, Kh, Kl, 1.0f, DMODEL, DMODEL, DMODEL, DMODEL);
        gemm_bf3<1><<<grid, 256, GSMEM>>>(Xh, Xl, Wh + 2L * WSZ, Wl + 2L * WSZ,
            nullptr, Vh, Vl, 1.0f, DMODEL, DMODEL, DMODEL, DMODEL);
    }

    // --- 2) Fused attention (writes pre-split O) ---
    {
        dim3 grid(SEQ / 128, BATCH * HEADS);
        attn_fused<<<grid, 256, ATT_SMEM>>>(Qh, Ql, Kh, Kl, Vh, Vl, Oh, Ol);
    }

    // --- 3) out = O @ Wo^T (fp32 out) ---
    {
        dim3 grid(DMODEL / 128, MTOT / 128);
        gemm_bf3<0><<<grid, 256, GSMEM>>>(Oh, Ol, Wh + 3L * WSZ, Wl + 3L * WSZ,
            out, nullptr, nullptr, 1.0f, DMODEL, DMODEL, DMODEL, DMODEL);
    }
}

// round 14
// speedup vs baseline: 1.3756x; 1.1035x over previous
#include <cuda_runtime.h>
#include <cuda_bf16.h>
#include <cuda_fp16.h>
#include <cstdint>

// ---------------------------------------------------------------------------
// MultiHeadAttention R14:
//  - pre-pass splits X and W into bf16 hi/lo once
//  - pure-bf16 cp.async double-buffered GEMM, 2 CTA/SM
//  - fused flash attention: QK bf16x3; PV fp16x2 (P single fp16, V fp16 hi/lo)
//  - O written pre-split bf16
// ---------------------------------------------------------------------------

#define BATCH   2
#define SEQ     2048
#define DMODEL  1024
#define HEADS   16
#define KDIM    64
#define MTOT    (BATCH * SEQ)           // 4096

// Scratch (device globals; allocation-free).
__device__ __nv_bfloat16 g_Xh[MTOT * DMODEL + 256];
__device__ __nv_bfloat16 g_Xl[MTOT * DMODEL + 256];
__device__ __nv_bfloat16 g_Wh[4 * DMODEL * DMODEL + 256];   // q,k,v,o
__device__ __nv_bfloat16 g_Wl[4 * DMODEL * DMODEL + 256];
__device__ __nv_bfloat16 g_Qh[MTOT * DMODEL + 256];
__device__ __nv_bfloat16 g_Ql[MTOT * DMODEL + 256];
__device__ __nv_bfloat16 g_Kh[MTOT * DMODEL + 256];
__device__ __nv_bfloat16 g_Kl[MTOT * DMODEL + 256];
__device__ __half        g_Vh[MTOT * DMODEL + 256];
__device__ __half        g_Vl[MTOT * DMODEL + 256];
__device__ __nv_bfloat16 g_Oh[MTOT * DMODEL + 256];
__device__ __nv_bfloat16 g_Ol[MTOT * DMODEL + 256];

// ======================= helpers ===========================================
__device__ __forceinline__ uint32_t smem_u32_of(const void* p) {
    uint32_t a;
    asm("{ .reg .u64 t; cvta.to.shared.u64 t, %1; cvt.u32.u64 %0, t; }"
        : "=r"(a) : "l"(p));
    return a;
}

__device__ __forceinline__ void ldmatrix_x4(uint32_t* r, uint32_t addr) {
    asm volatile("ldmatrix.sync.aligned.m8n8.x4.shared.b16 {%0,%1,%2,%3}, [%4];"
        : "=r"(r[0]), "=r"(r[1]), "=r"(r[2]), "=r"(r[3]) : "r"(addr));
}
__device__ __forceinline__ void ldmatrix_x4_t(uint32_t* r, uint32_t addr) {
    asm volatile("ldmatrix.sync.aligned.m8n8.x4.trans.shared.b16 {%0,%1,%2,%3}, [%4];"
        : "=r"(r[0]), "=r"(r[1]), "=r"(r[2]), "=r"(r[3]) : "r"(addr));
}

__device__ __forceinline__ void mma_bf16(float* c, const uint32_t* a, const uint32_t* b) {
    asm volatile(
        "mma.sync.aligned.m16n8k16.row.col.f32.bf16.bf16.f32 "
        "{%0,%1,%2,%3}, {%4,%5,%6,%7}, {%8,%9}, {%0,%1,%2,%3};"
        : "+f"(c[0]), "+f"(c[1]), "+f"(c[2]), "+f"(c[3])
        : "r"(a[0]), "r"(a[1]), "r"(a[2]), "r"(a[3]), "r"(b[0]), "r"(b[1]));
}
__device__ __forceinline__ void mma_fp16(float* c, const uint32_t* a, const uint32_t* b) {
    asm volatile(
        "mma.sync.aligned.m16n8k16.row.col.f32.f16.f16.f32 "
        "{%0,%1,%2,%3}, {%4,%5,%6,%7}, {%8,%9}, {%0,%1,%2,%3};"
        : "+f"(c[0]), "+f"(c[1]), "+f"(c[2]), "+f"(c[3])
        : "r"(a[0]), "r"(a[1]), "r"(a[2]), "r"(a[3]), "r"(b[0]), "r"(b[1]));
}

#define CP_ASYNC16(dst, src) \
    asm volatile("cp.async.cg.shared.global [%0], [%1], 16;" \
                 :: "r"(dst), "l"(src) : "memory")
#define CP_COMMIT() asm volatile("cp.async.commit_group;" ::: "memory")
#define CP_WAIT1()  asm volatile("cp.async.wait_group 1;" ::: "memory")
#define CP_WAIT0()  asm volatile("cp.async.wait_group 0;" ::: "memory")

__device__ __forceinline__ float ex2(float x) {
    float r;
    asm("ex2.approx.ftz.f32 %0, %1;" : "=f"(r) : "f"(x));
    return r;
}

__device__ __forceinline__ void split2(float x, float y, uint32_t& hi, uint32_t& lo) {
    __nv_bfloat16 hx = __float2bfloat16(x);
    __nv_bfloat16 hy = __float2bfloat16(y);
    __nv_bfloat162 h; h.x = hx; h.y = hy;
    hi = *reinterpret_cast<uint32_t*>(&h);
    __nv_bfloat162 l = __floats2bfloat162_rn(x - __bfloat162float(hx),
                                             y - __bfloat162float(hy));
    lo = *reinterpret_cast<uint32_t*>(&l);
}

__device__ __forceinline__ void split2h(float x, float y, uint32_t& hi, uint32_t& lo) {
    __half hx = __float2half_rn(x);
    __half hy = __float2half_rn(y);
    __half2 h; h.x = hx; h.y = hy;
    hi = *reinterpret_cast<uint32_t*>(&h);
    __half2 l = __floats2half2_rn(x - __half2float(hx), y - __half2float(hy));
    lo = *reinterpret_cast<uint32_t*>(&l);
}

__device__ __forceinline__ uint32_t pack2h(float x, float y) {
    __half2 h = __floats2half2_rn(x, y);
    return *reinterpret_cast<uint32_t*>(&h);
}

// ======================= pre-pass: fp32 -> bf16 hi/lo ======================
__global__ __launch_bounds__(256)
void conv_split(const float* __restrict__ s,
                __nv_bfloat16* __restrict__ h, __nv_bfloat16* __restrict__ l,
                int n4)
{
    const int i = blockIdx.x * blockDim.x + threadIdx.x;
    if (i < n4) {
        float4 v = reinterpret_cast<const float4*>(s)[i];
        uint32_t h0, l0, h1, l1;
        split2(v.x, v.y, h0, l0);
        split2(v.z, v.w, h1, l1);
        uint2 hh; hh.x = h0; hh.y = h1;
        uint2 ll; ll.x = l0; ll.y = l1;
        reinterpret_cast<uint2*>(h)[i] = hh;
        reinterpret_cast<uint2*>(l)[i] = ll;
    }
}

// ======================= pure-bf16 warp-MMA GEMM ===========================
// C[m,n] = alpha * sum_k A[m,k]*B[n,k] with A,B as bf16 hi/lo pairs.
// SPLIT=0: fp32 C. SPLIT=1: bf16 hi/lo. SPLIT=2: fp16 hi/lo (for V).
#define LDSR 40                     // bf16 row stride (80 B)
#define GBUF 10240                  // 128 * 80 B
#define GSTG (4 * GBUF)
#define GSMEM (2 * GSTG)            // 81920 B

template <int SPLIT>
__global__ __launch_bounds__(256, 2)
void gemm_bf3(const __nv_bfloat16* __restrict__ Ah, const __nv_bfloat16* __restrict__ Al,
              const __nv_bfloat16* __restrict__ Bh, const __nv_bfloat16* __restrict__ Bl,
              float* __restrict__ C,
              __nv_bfloat16* __restrict__ Chi, __nv_bfloat16* __restrict__ Clo,
              __half* __restrict__ Chf, __half* __restrict__ Clf,
              float alpha, int K, int lda, int ldb, int ldc)
{
    extern __shared__ char dsm[];
    const uint32_t sb = smem_u32_of(dsm);

    const int tid  = threadIdx.x;
    const int wid  = tid >> 5;
    const int lane = tid & 31;
    const int m0   = blockIdx.y * 128;
    const int n0   = blockIdx.x * 128;
    const int warp_m = wid & 3;
    const int warp_n = wid >> 2;

    float acc[2][8][4];
    #pragma unroll
    for (int i = 0; i < 2; i++)
        #pragma unroll
        for (int j = 0; j < 8; j++)
            #pragma unroll
            for (int q = 0; q < 4; q++) acc[i][j][q] = 0.f;

    const int r  = tid >> 1;
    const int cb = (tid & 1) * 32;
    const uint32_t drow = (uint32_t)(r * 80) + cb;
    const char* pAh = (const char*)(Ah + (long)(m0 + r) * lda) + cb;
    const char* pAl = (const char*)(Al + (long)(m0 + r) * lda) + cb;
    const char* pBh = (const char*)(Bh + (long)(n0 + r) * ldb) + cb;
    const char* pBl = (const char*)(Bl + (long)(n0 + r) * ldb) + cb;

    const int NC = K / 32;

    {
        const uint32_t s0 = sb;
        CP_ASYNC16(s0 + 0 * GBUF + drow,      pAh);
        CP_ASYNC16(s0 + 0 * GBUF + drow + 16, pAh + 16);
        CP_ASYNC16(s0 + 1 * GBUF + drow,      pAl);
        CP_ASYNC16(s0 + 1 * GBUF + drow + 16, pAl + 16);
        CP_ASYNC16(s0 + 2 * GBUF + drow,      pBh);
        CP_ASYNC16(s0 + 2 * GBUF + drow + 16, pBh + 16);
        CP_ASYNC16(s0 + 3 * GBUF + drow,      pBl);
        CP_ASYNC16(s0 + 3 * GBUF + drow + 16, pBl + 16);
        CP_COMMIT();
    }

    for (int c = 0; c < NC; c++) {
        if (c + 1 < NC) {
            const uint32_t s1 = sb + ((c + 1) & 1) * GSTG;
            const long go = (long)(c + 1) * 64;
            CP_ASYNC16(s1 + 0 * GBUF + drow,      pAh + go);
            CP_ASYNC16(s1 + 0 * GBUF + drow + 16, pAh + go + 16);
            CP_ASYNC16(s1 + 1 * GBUF + drow,      pAl + go);
            CP_ASYNC16(s1 + 1 * GBUF + drow + 16, pAl + go + 16);
            CP_ASYNC16(s1 + 2 * GBUF + drow,      pBh + go);
            CP_ASYNC16(s1 + 2 * GBUF + drow + 16, pBh + go + 16);
            CP_ASYNC16(s1 + 3 * GBUF + drow,      pBl + go);
            CP_ASYNC16(s1 + 3 * GBUF + drow + 16, pBl + go + 16);
            CP_COMMIT();
            CP_WAIT1();
        } else {
            CP_WAIT0();
        }
        __syncthreads();

        const uint32_t cur = sb + (c & 1) * GSTG;
        const uint32_t sAhi = cur, sAlo = cur + GBUF;
        const uint32_t sBhi = cur + 2 * GBUF, sBlo = cur + 3 * GBUF;

        #pragma unroll
        for (int ks = 0; ks < 32; ks += 16) {
            uint32_t ah[2][4], al[2][4];
            #pragma unroll
            for (int mi = 0; mi < 2; mi++) {
                const int row = warp_m * 32 + mi * 16 + (lane & 15);
                const int col = ks + (lane >> 4) * 8;
                const uint32_t off = (uint32_t)(row * LDSR + col) * 2;
                ldmatrix_x4(ah[mi], sAhi + off);
                ldmatrix_x4(al[mi], sAlo + off);
            }
            #pragma unroll
            for (int ng = 0; ng < 4; ng++) {
                const int nb   = warp_n * 64 + ng * 16;
                const int nrow = nb + (lane & 7) + ((lane >> 4) << 3);
                const int kcol = ks + ((lane >> 3) & 1) * 8;
                const uint32_t off = (uint32_t)(nrow * LDSR + kcol) * 2;
                uint32_t bh[4], bl[4];
                ldmatrix_x4(bh, sBhi + off);
                ldmatrix_x4(bl, sBlo + off);
                #pragma unroll
                for (int mi = 0; mi < 2; mi++) {
                    #pragma unroll
                    for (int nt = 0; nt < 2; nt++) {
                        float* cc = acc[mi][ng * 2 + nt];
                        mma_bf16(cc, ah[mi], bh + nt * 2);
                        mma_bf16(cc, ah[mi], bl + nt * 2);
                        mma_bf16(cc, al[mi], bh + nt * 2);
                    }
                }
            }
        }
        __syncthreads();
    }

    // ---- epilogue ----
    const int g  = lane >> 2;
    const int tg = lane & 3;
    #pragma unroll
    for (int mi = 0; mi < 2; mi++) {
        const int row = m0 + warp_m * 32 + mi * 16 + g;
        #pragma unroll
        for (int nt = 0; nt < 8; nt++) {
            const int col = n0 + warp_n * 64 + nt * 8 + tg * 2;
            if (SPLIT == 1) {
                uint32_t hi, lo;
                split2(acc[mi][nt][0] * alpha, acc[mi][nt][1] * alpha, hi, lo);
                *reinterpret_cast<uint32_t*>(Chi + (long)row * ldc + col) = hi;
                *reinterpret_cast<uint32_t*>(Clo + (long)row * ldc + col) = lo;
                split2(acc[mi][nt][2] * alpha, acc[mi][nt][3] * alpha, hi, lo);
                *reinterpret_cast<uint32_t*>(Chi + (long)(row + 8) * ldc + col) = hi;
                *reinterpret_cast<uint32_t*>(Clo + (long)(row + 8) * ldc + col) = lo;
            } else if (SPLIT == 2) {
                uint32_t hi, lo;
                split2h(acc[mi][nt][0] * alpha, acc[mi][nt][1] * alpha, hi, lo);
                *reinterpret_cast<uint32_t*>(Chf + (long)row * ldc + col) = hi;
                *reinterpret_cast<uint32_t*>(Clf + (long)row * ldc + col) = lo;
                split2h(acc[mi][nt][2] * alpha, acc[mi][nt][3] * alpha, hi, lo);
                *reinterpret_cast<uint32_t*>(Chf + (long)(row + 8) * ldc + col) = hi;
                *reinterpret_cast<uint32_t*>(Clf + (long)(row + 8) * ldc + col) = lo;
            } else {
                float2 v0, v1;
                v0.x = acc[mi][nt][0]; v0.y = acc[mi][nt][1];
                v1.x = acc[mi][nt][2]; v1.y = acc[mi][nt][3];
                *reinterpret_cast<float2*>(C + (long)row * ldc + col) = v0;
                *reinterpret_cast<float2*>(C + (long)(row + 8) * ldc + col) = v1;
            }
        }
    }
}

// ======================= fused flash attention =============================
// Grid: (SEQ/128, BATCH*HEADS). 256 threads = 8 warps; warp w owns 16 q-rows.
// QK bf16x3; PV fp16x2 (P single fp16, V fp16 hi/lo).
#define LDKV 72          // 16-bit-elem row stride (144 B)
#define TILE_B 18432

#define ATT_QH 0
#define ATT_QL TILE_B
#define ATT_ST 36864
#define STG_SZ (4 * TILE_B)
#define ATT_SMEM (ATT_ST + 2 * STG_SZ)   // 184320

__global__ __launch_bounds__(256)
void attn_fused(const __nv_bfloat16* __restrict__ Qh, const __nv_bfloat16* __restrict__ Ql,
                const __nv_bfloat16* __restrict__ Kh, const __nv_bfloat16* __restrict__ Kl,
                const __half* __restrict__ Vh, const __half* __restrict__ Vl,
                __nv_bfloat16* __restrict__ Oh, __nv_bfloat16* __restrict__ Ol)
{
    extern __shared__ char dsm[];
    const uint32_t sb = smem_u32_of(dsm);

    const int tid  = threadIdx.x;
    const int wid  = tid >> 5;
    const int lane = tid & 31;
    const int g    = lane >> 2;
    const int tg   = lane & 3;

    const int bh = blockIdx.y;
    const int b  = bh >> 4;
    const int h  = bh & 15;
    const int q0 = blockIdx.x * 128;

    const long headoff = (long)h * KDIM;
    const __nv_bfloat16* Qhp = Qh + ((long)(b * SEQ + q0)) * DMODEL + headoff;
    const __nv_bfloat16* Qlp = Ql + ((long)(b * SEQ + q0)) * DMODEL + headoff;
    const __nv_bfloat16* Khp = Kh + ((long)(b * SEQ)) * DMODEL + headoff;
    const __nv_bfloat16* Klp = Kl + ((long)(b * SEQ)) * DMODEL + headoff;
    const __half*        Vhp = Vh + ((long)(b * SEQ)) * DMODEL + headoff;
    const __half*        Vlp = Vl + ((long)(b * SEQ)) * DMODEL + headoff;

    const int row = tid >> 1;
    const int cb  = (tid & 1) * 64;
    const uint32_t drow = (uint32_t)(row * (LDKV * 2)) + cb;

    // ---- issue Q + stage0 K/V ----
    {
        const char* qs_h = (const char*)(Qhp + (long)row * DMODEL) + cb;
        const char* qs_l = (const char*)(Qlp + (long)row * DMODEL) + cb;
        #pragma unroll
        for (int c = 0; c < 4; c++) {
            CP_ASYNC16(sb + ATT_QH + drow + c * 16, qs_h + c * 16);
            CP_ASYNC16(sb + ATT_QL + drow + c * 16, qs_l + c * 16);
        }
        const char* ks_h = (const char*)(Khp + (long)row * DMODEL) + cb;
        const char* ks_l = (const char*)(Klp + (long)row * DMODEL) + cb;
        const char* vs_h = (const char*)(Vhp + (long)row * DMODEL) + cb;
        const char* vs_l = (const char*)(Vlp + (long)row * DMODEL) + cb;
        const uint32_t s0 = sb + ATT_ST;
        #pragma unroll
        for (int c = 0; c < 4; c++) {
            CP_ASYNC16(s0 + 0 * TILE_B + drow + c * 16, ks_h + c * 16);
            CP_ASYNC16(s0 + 1 * TILE_B + drow + c * 16, ks_l + c * 16);
            CP_ASYNC16(s0 + 2 * TILE_B + drow + c * 16, vs_h + c * 16);
            CP_ASYNC16(s0 + 3 * TILE_B + drow + c * 16, vs_l + c * 16);
        }
        CP_COMMIT();
    }

    uint32_t qh[4][4], ql[4][4];
    float m_run[2] = {-1e30f, -1e30f};
    float l_run[2] = {0.f, 0.f};
    float acc_o[8][4];
    #pragma unroll
    for (int i = 0; i < 8; i++)
        #pragma unroll
        for (int q = 0; q < 4; q++) acc_o[i][q] = 0.f;

    const int NT = SEQ / 128;

    for (int t = 0; t < NT; t++) {
        if (t + 1 < NT) {
            const long rbase = (long)((t + 1) * 128 + row) * DMODEL;
            const char* ks_h = (const char*)(Khp + rbase) + cb;
            const char* ks_l = (const char*)(Klp + rbase) + cb;
            const char* vs_h = (const char*)(Vhp + rbase) + cb;
            const char* vs_l = (const char*)(Vlp + rbase) + cb;
            const uint32_t s1 = sb + ATT_ST + ((t + 1) & 1) * STG_SZ;
            #pragma unroll
            for (int c = 0; c < 4; c++) {
                CP_ASYNC16(s1 + 0 * TILE_B + drow + c * 16, ks_h + c * 16);
                CP_ASYNC16(s1 + 1 * TILE_B + drow + c * 16, ks_l + c * 16);
                CP_ASYNC16(s1 + 2 * TILE_B + drow + c * 16, vs_h + c * 16);
                CP_ASYNC16(s1 + 3 * TILE_B + drow + c * 16, vs_l + c * 16);
            }
            CP_COMMIT();
            CP_WAIT1();
        } else {
            CP_WAIT0();
        }
        __syncthreads();

        const uint32_t cur = sb + ATT_ST + (t & 1) * STG_SZ;
        const uint32_t sKh = cur, sKl = cur + TILE_B;
        const uint32_t sVh = cur + 2 * TILE_B, sVl = cur + 3 * TILE_B;

        if (t == 0) {
            #pragma unroll
            for (int ks = 0; ks < 4; ks++) {
                const int qrow = wid * 16 + (lane & 15);
                const int qcol = ks * 16 + (lane >> 4) * 8;
                const uint32_t off = (uint32_t)(qrow * LDKV + qcol) * 2;
                ldmatrix_x4(qh[ks], sb + ATT_QH + off);
                ldmatrix_x4(ql[ks], sb + ATT_QL + off);
            }
        }

        // ---- S = Q K^T (bf16x3) ----
        float s_acc[16][4];
        #pragma unroll
        for (int tt = 0; tt < 16; tt++)
            #pragma unroll
            for (int q = 0; q < 4; q++) s_acc[tt][q] = 0.f;

        #pragma unroll
        for (int ks = 0; ks < 4; ks++) {
            #pragma unroll
            for (int ng = 0; ng < 8; ng++) {
                const int nrow = ng * 16 + (lane & 7) + ((lane >> 4) << 3);
                const int kcol = ks * 16 + ((lane >> 3) & 1) * 8;
                const uint32_t off = (uint32_t)(nrow * LDKV + kcol) * 2;
                uint32_t bh4[4], bl4[4];
                ldmatrix_x4(bh4, sKh + off);
                ldmatrix_x4(bl4, sKl + off);
                #pragma unroll
                for (int nt = 0; nt < 2; nt++) {
                    float* c = s_acc[ng * 2 + nt];
                    mma_bf16(c, qh[ks], bh4 + nt * 2);
                    mma_bf16(c, qh[ks], bl4 + nt * 2);
                    mma_bf16(c, ql[ks], bh4 + nt * 2);
                }
            }
        }

        // ---- online softmax (base-2) ----
        float mnew0 = m_run[0], mnew1 = m_run[1];
        #pragma unroll
        for (int tt = 0; tt < 16; tt++) {
            mnew0 = fmaxf(mnew0, fmaxf(s_acc[tt][0], s_acc[tt][1]));
            mnew1 = fmaxf(mnew1, fmaxf(s_acc[tt][2], s_acc[tt][3]));
        }
        mnew0 = fmaxf(mnew0, __shfl_xor_sync(0xFFFFFFFFu, mnew0, 1));
        mnew0 = fmaxf(mnew0, __shfl_xor_sync(0xFFFFFFFFu, mnew0, 2));
        mnew1 = fmaxf(mnew1, __shfl_xor_sync(0xFFFFFFFFu, mnew1, 1));
        mnew1 = fmaxf(mnew1, __shfl_xor_sync(0xFFFFFFFFu, mnew1, 2));

        const float fac0 = ex2(m_run[0] - mnew0);
        const float fac1 = ex2(m_run[1] - mnew1);
        m_run[0] = mnew0; m_run[1] = mnew1;
        l_run[0] *= fac0; l_run[1] *= fac1;
        #pragma unroll
        for (int i = 0; i < 8; i++) {
            acc_o[i][0] *= fac0; acc_o[i][1] *= fac0;
            acc_o[i][2] *= fac1; acc_o[i][3] *= fac1;
        }

        // ---- P = exp2(S - m); pack single fp16 A-fragments ----
        uint32_t ph[8][4];
        float rs0 = 0.f, rs1 = 0.f;
        #pragma unroll
        for (int tt = 0; tt < 16; tt++) {
            const float p0 = ex2(s_acc[tt][0] - mnew0);
            const float p1 = ex2(s_acc[tt][1] - mnew0);
            const float p2 = ex2(s_acc[tt][2] - mnew1);
            const float p3 = ex2(s_acc[tt][3] - mnew1);
            rs0 += p0 + p1;
            rs1 += p2 + p3;
            const int kk = tt >> 1, half = tt & 1;
            ph[kk][2 * half]     = pack2h(p0, p1);
            ph[kk][2 * half + 1] = pack2h(p2, p3);
        }
        rs0 += __shfl_xor_sync(0xFFFFFFFFu, rs0, 1);
        rs0 += __shfl_xor_sync(0xFFFFFFFFu, rs0, 2);
        rs1 += __shfl_xor_sync(0xFFFFFFFFu, rs1, 1);
        rs1 += __shfl_xor_sync(0xFFFFFFFFu, rs1, 2);
        l_run[0] += rs0; l_run[1] += rs1;

        // ---- O += P V (fp16x2: p*vh + p*vl) ----
        #pragma unroll
        for (int kk = 0; kk < 8; kk++) {
            #pragma unroll
            for (int ndp = 0; ndp < 4; ndp++) {
                const int krow = kk * 16 + ((lane >> 3) & 1) * 8 + (lane & 7);
                const int ncol = ndp * 16 + ((lane >> 4) << 3);
                const uint32_t off = (uint32_t)(krow * LDKV + ncol) * 2;
                uint32_t vh4[4], vl4[4];
                ldmatrix_x4_t(vh4, sVh + off);
                ldmatrix_x4_t(vl4, sVl + off);
                #pragma unroll
                for (int nt = 0; nt < 2; nt++) {
                    float* c = acc_o[ndp * 2 + nt];
                    mma_fp16(c, ph[kk], vh4 + nt * 2);
                    mma_fp16(c, ph[kk], vl4 + nt * 2);
                }
            }
        }
        __syncthreads();
    }

    // ---- epilogue: O /= l, write pre-split bf16 hi/lo ----
    const float inv0 = 1.0f / l_run[0];
    const float inv1 = 1.0f / l_run[1];
    const long row0 = (long)(b * SEQ + q0 + wid * 16 + g);
    #pragma unroll
    for (int nt = 0; nt < 8; nt++) {
        const int col = h * KDIM + nt * 8 + tg * 2;
        uint32_t hi, lo;
        split2(acc_o[nt][0] * inv0, acc_o[nt][1] * inv0, hi, lo);
        *reinterpret_cast<uint32_t*>(Oh + row0 * DMODEL + col) = hi;
        *reinterpret_cast<uint32_t*>(Ol + row0 * DMODEL + col) = lo;
        split2(acc_o[nt][2] * inv1, acc_o[nt][3] * inv1, hi, lo);
        *reinterpret_cast<uint32_t*>(Oh + (row0 + 8) * DMODEL + col) = hi;
        *reinterpret_cast<uint32_t*>(Ol + (row0 + 8) * DMODEL + col) = lo;
    }
}

// ---------------------------------------------------------------------------
extern "C" void kernel_launch(void* const* d_in, const int* in_sizes, int n_in,
                              void* d_out, int out_size)
{
    const float* X  = (const float*)d_in[0];
    const float* Wq = (const float*)d_in[1];
    const float* Wk = (const float*)d_in[2];
    const float* Wv = (const float*)d_in[3];
    const float* Wo = (const float*)d_in[4];
    float* out = (float*)d_out;

    __nv_bfloat16 *Xh, *Xl, *Wh, *Wl, *Qh, *Ql, *Kh, *Kl, *Oh, *Ol;
    __half *Vh, *Vl;
    cudaGetSymbolAddress((void**)&Xh, g_Xh);
    cudaGetSymbolAddress((void**)&Xl, g_Xl);
    cudaGetSymbolAddress((void**)&Wh, g_Wh);
    cudaGetSymbolAddress((void**)&Wl, g_Wl);
    cudaGetSymbolAddress((void**)&Qh, g_Qh);
    cudaGetSymbolAddress((void**)&Ql, g_Ql);
    cudaGetSymbolAddress((void**)&Kh, g_Kh);
    cudaGetSymbolAddress((void**)&Kl, g_Kl);
    cudaGetSymbolAddress((void**)&Vh, g_Vh);
    cudaGetSymbolAddress((void**)&Vl, g_Vl);
    cudaGetSymbolAddress((void**)&Oh, g_Oh);
    cudaGetSymbolAddress((void**)&Ol, g_Ol);

    cudaFuncSetAttribute(attn_fused,
                         cudaFuncAttributeMaxDynamicSharedMemorySize, ATT_SMEM);
    cudaFuncSetAttribute(gemm_bf3<0>,
                         cudaFuncAttributeMaxDynamicSharedMemorySize, GSMEM);
    cudaFuncSetAttribute(gemm_bf3<1>,
                         cudaFuncAttributeMaxDynamicSharedMemorySize, GSMEM);
    cudaFuncSetAttribute(gemm_bf3<2>,
                         cudaFuncAttributeMaxDynamicSharedMemorySize, GSMEM);

    const float SC = 0.125f * 1.4426950408889634f;
    const int WSZ = DMODEL * DMODEL;

    // --- 0) pre-split X and weights ---
    {
        const int n4x = MTOT * DMODEL / 4;
        conv_split<<<n4x / 256, 256>>>(X, Xh, Xl, n4x);
        const int n4w = WSZ / 4;
        conv_split<<<n4w / 256, 256>>>(Wq, Wh + 0L * WSZ, Wl + 0L * WSZ, n4w);
        conv_split<<<n4w / 256, 256>>>(Wk, Wh + 1L * WSZ, Wl + 1L * WSZ, n4w);
        conv_split<<<n4w / 256, 256>>>(Wv, Wh + 2L * WSZ, Wl + 2L * WSZ, n4w);
        conv_split<<<n4w / 256, 256>>>(Wo, Wh + 3L * WSZ, Wl + 3L * WSZ, n4w);
    }

    // --- 1) Projections (pure bf16; Q pre-scaled; V emitted fp16) ---
    {
        dim3 grid(DMODEL / 128, MTOT / 128);
        gemm_bf3<1><<<grid, 256, GSMEM>>>(Xh, Xl, Wh + 0L * WSZ, Wl + 0L * WSZ,
            nullptr, Qh, Ql, nullptr, nullptr, SC, DMODEL, DMODEL, DMODEL, DMODEL);
        gemm_bf3<1><<<grid, 256, GSMEM>>>(Xh, Xl, Wh + 1L * WSZ, Wl + 1L * WSZ,
            nullptr, Kh, Kl, nullptr, nullptr, 1.0f, DMODEL, DMODEL, DMODEL, DMODEL);
        gemm_bf3<2><<<grid, 256, GSMEM>>>(Xh, Xl, Wh + 2L * WSZ, Wl + 2L * WSZ,
            nullptr, nullptr, nullptr, Vh, Vl, 1.0f, DMODEL, DMODEL, DMODEL, DMODEL);
    }

    // --- 2) Fused attention (writes pre-split O) ---
    {
        dim3 grid(SEQ / 128, BATCH * HEADS);
        attn_fused<<<grid, 256, ATT_SMEM>>>(Qh, Ql, Kh, Kl, Vh, Vl, Oh, Ol);
    }

    // --- 3) out = O @ Wo^T (fp32 out) ---
    {
        dim3 grid(DMODEL / 128, MTOT / 128);
        gemm_bf3<0><<<grid, 256, GSMEM>>>(Oh, Ol, Wh + 3L * WSZ, Wl + 3L * WSZ,
            out, nullptr, nullptr, nullptr, nullptr, 1.0f, DMODEL, DMODEL, DMODEL, DMODEL);
    }
}

// round 17
// speedup vs baseline: 1.6386x; 1.1912x over previous
#include <cuda_runtime.h>
#include <cuda_bf16.h>
#include <cuda_fp16.h>
#include <cstdint>

// ---------------------------------------------------------------------------
// MultiHeadAttention R15:
//  - X pre-split fp16 hi/lo; W pre-rounded single fp16
//  - GEMMs fp16x2 (Xh*W + Xl*W): 2 MMAs per step, 3 SMEM buffers
//  - attention: QK bf16x3 (unchanged), PV fp16x2, O emitted fp16 hi/lo
// ---------------------------------------------------------------------------

#define BATCH   2
#define SEQ     2048
#define DMODEL  1024
#define HEADS   16
#define KDIM    64
#define MTOT    (BATCH * SEQ)           // 4096

// Scratch (device globals; allocation-free).
__device__ __half        g_Xh[MTOT * DMODEL + 256];
__device__ __half        g_Xl[MTOT * DMODEL + 256];
__device__ __half        g_W [4 * DMODEL * DMODEL + 256];   // q,k,v,o (fp16)
__device__ __nv_bfloat16 g_Qh[MTOT * DMODEL + 256];
__device__ __nv_bfloat16 g_Ql[MTOT * DMODEL + 256];
__device__ __nv_bfloat16 g_Kh[MTOT * DMODEL + 256];
__device__ __nv_bfloat16 g_Kl[MTOT * DMODEL + 256];
__device__ __half        g_Vh[MTOT * DMODEL + 256];
__device__ __half        g_Vl[MTOT * DMODEL + 256];
__device__ __half        g_Oh[MTOT * DMODEL + 256];
__device__ __half        g_Ol[MTOT * DMODEL + 256];

// ======================= helpers ===========================================
__device__ __forceinline__ uint32_t smem_u32_of(const void* p) {
    uint32_t a;
    asm("{ .reg .u64 t; cvta.to.shared.u64 t, %1; cvt.u32.u64 %0, t; }"
        : "=r"(a) : "l"(p));
    return a;
}

__device__ __forceinline__ void ldmatrix_x4(uint32_t* r, uint32_t addr) {
    asm volatile("ldmatrix.sync.aligned.m8n8.x4.shared.b16 {%0,%1,%2,%3}, [%4];"
        : "=r"(r[0]), "=r"(r[1]), "=r"(r[2]), "=r"(r[3]) : "r"(addr));
}
__device__ __forceinline__ void ldmatrix_x4_t(uint32_t* r, uint32_t addr) {
    asm volatile("ldmatrix.sync.aligned.m8n8.x4.trans.shared.b16 {%0,%1,%2,%3}, [%4];"
        : "=r"(r[0]), "=r"(r[1]), "=r"(r[2]), "=r"(r[3]) : "r"(addr));
}

__device__ __forceinline__ void mma_bf16(float* c, const uint32_t* a, const uint32_t* b) {
    asm volatile(
        "mma.sync.aligned.m16n8k16.row.col.f32.bf16.bf16.f32 "
        "{%0,%1,%2,%3}, {%4,%5,%6,%7}, {%8,%9}, {%0,%1,%2,%3};"
        : "+f"(c[0]), "+f"(c[1]), "+f"(c[2]), "+f"(c[3])
        : "r"(a[0]), "r"(a[1]), "r"(a[2]), "r"(a[3]), "r"(b[0]), "r"(b[1]));
}
__device__ __forceinline__ void mma_fp16(float* c, const uint32_t* a, const uint32_t* b) {
    asm volatile(
        "mma.sync.aligned.m16n8k16.row.col.f32.f16.f16.f32 "
        "{%0,%1,%2,%3}, {%4,%5,%6,%7}, {%8,%9}, {%0,%1,%2,%3};"
        : "+f"(c[0]), "+f"(c[1]), "+f"(c[2]), "+f"(c[3])
        : "r"(a[0]), "r"(a[1]), "r"(a[2]), "r"(a[3]), "r"(b[0]), "r"(b[1]));
}

#define CP_ASYNC16(dst, src) \
    asm volatile("cp.async.cg.shared.global [%0], [%1], 16;" \
                 :: "r"(dst), "l"(src) : "memory")
#define CP_COMMIT() asm volatile("cp.async.commit_group;" ::: "memory")
#define CP_WAIT1()  asm volatile("cp.async.wait_group 1;" ::: "memory")
#define CP_WAIT0()  asm volatile("cp.async.wait_group 0;" ::: "memory")

__device__ __forceinline__ float ex2(float x) {
    float r;
    asm("ex2.approx.ftz.f32 %0, %1;" : "=f"(r) : "f"(x));
    return r;
}

__device__ __forceinline__ void split2(float x, float y, uint32_t& hi, uint32_t& lo) {
    __nv_bfloat16 hx = __float2bfloat16(x);
    __nv_bfloat16 hy = __float2bfloat16(y);
    __nv_bfloat162 h; h.x = hx; h.y = hy;
    hi = *reinterpret_cast<uint32_t*>(&h);
    __nv_bfloat162 l = __floats2bfloat162_rn(x - __bfloat162float(hx),
                                             y - __bfloat162float(hy));
    lo = *reinterpret_cast<uint32_t*>(&l);
}

__device__ __forceinline__ void split2h(float x, float y, uint32_t& hi, uint32_t& lo) {
    __half hx = __float2half_rn(x);
    __half hy = __float2half_rn(y);
    __half2 h; h.x = hx; h.y = hy;
    hi = *reinterpret_cast<uint32_t*>(&h);
    __half2 l = __floats2half2_rn(x - __half2float(hx), y - __half2float(hy));
    lo = *reinterpret_cast<uint32_t*>(&l);
}

__device__ __forceinline__ uint32_t pack2h(float x, float y) {
    __half2 h = __floats2half2_rn(x, y);
    return *reinterpret_cast<uint32_t*>(&h);
}

// ======================= pre-pass kernels ==================================
__global__ __launch_bounds__(256)
void conv_split_h(const float* __restrict__ s,
                  __half* __restrict__ h, __half* __restrict__ l, int n4)
{
    const int i = blockIdx.x * blockDim.x + threadIdx.x;
    if (i < n4) {
        float4 v = reinterpret_cast<const float4*>(s)[i];
        uint32_t h0, l0, h1, l1;
        split2h(v.x, v.y, h0, l0);
        split2h(v.z, v.w, h1, l1);
        uint2 hh; hh.x = h0; hh.y = h1;
        uint2 ll; ll.x = l0; ll.y = l1;
        reinterpret_cast<uint2*>(h)[i] = hh;
        reinterpret_cast<uint2*>(l)[i] = ll;
    }
}

__global__ __launch_bounds__(256)
void conv_h(const float* __restrict__ s, __half* __restrict__ h, int n4)
{
    const int i = blockIdx.x * blockDim.x + threadIdx.x;
    if (i < n4) {
        float4 v = reinterpret_cast<const float4*>(s)[i];
        uint2 hh;
        hh.x = pack2h(v.x, v.y);
        hh.y = pack2h(v.z, v.w);
        reinterpret_cast<uint2*>(h)[i] = hh;
    }
}

// ======================= fp16x2 warp-MMA GEMM ==============================
// C[m,n] = alpha * sum_k (Ah+Al)[m,k] * B[n,k], A fp16 hi/lo, B single fp16.
// Tile 128x128, K-chunk 32, 256 thr (4x2 warps), cp.async 2-stage.
// SPLIT=0: fp32 C. SPLIT=1: bf16 hi/lo. SPLIT=2: fp16 hi/lo.
#define LDSR 40                     // 16-bit-elem row stride (80 B)
#define GBUF 10240                  // 128 * 80 B
#define GSTG (3 * GBUF)             // Ah, Al, B
#define GSMEM (2 * GSTG)            // 61440 B

template <int SPLIT>
__global__ __launch_bounds__(256, 2)
void gemm_f2(const __half* __restrict__ Ah, const __half* __restrict__ Al,
             const __half* __restrict__ B,
             float* __restrict__ C,
             __nv_bfloat16* __restrict__ Cbh, __nv_bfloat16* __restrict__ Cbl,
             __half* __restrict__ Chh, __half* __restrict__ Chl,
             float alpha, int K, int lda, int ldb, int ldc)
{
    extern __shared__ char dsm[];
    const uint32_t sb = smem_u32_of(dsm);

    const int tid  = threadIdx.x;
    const int wid  = tid >> 5;
    const int lane = tid & 31;
    const int m0   = blockIdx.y * 128;
    const int n0   = blockIdx.x * 128;
    const int warp_m = wid & 3;
    const int warp_n = wid >> 2;

    float acc[2][8][4];
    #pragma unroll
    for (int i = 0; i < 2; i++)
        #pragma unroll
        for (int j = 0; j < 8; j++)
            #pragma unroll
            for (int q = 0; q < 4; q++) acc[i][j][q] = 0.f;

    const int r  = tid >> 1;
    const int cb = (tid & 1) * 32;
    const uint32_t drow = (uint32_t)(r * 80) + cb;
    const char* pAh = (const char*)(Ah + (long)(m0 + r) * lda) + cb;
    const char* pAl = (const char*)(Al + (long)(m0 + r) * lda) + cb;
    const char* pB  = (const char*)(B  + (long)(n0 + r) * ldb) + cb;

    const int NC = K / 32;

    {
        const uint32_t s0 = sb;
        CP_ASYNC16(s0 + 0 * GBUF + drow,      pAh);
        CP_ASYNC16(s0 + 0 * GBUF + drow + 16, pAh + 16);
        CP_ASYNC16(s0 + 1 * GBUF + drow,      pAl);
        CP_ASYNC16(s0 + 1 * GBUF + drow + 16, pAl + 16);
        CP_ASYNC16(s0 + 2 * GBUF + drow,      pB);
        CP_ASYNC16(s0 + 2 * GBUF + drow + 16, pB + 16);
        CP_COMMIT();
    }

    for (int c = 0; c < NC; c++) {
        if (c + 1 < NC) {
            const uint32_t s1 = sb + ((c + 1) & 1) * GSTG;
            const long go = (long)(c + 1) * 64;
            CP_ASYNC16(s1 + 0 * GBUF + drow,      pAh + go);
            CP_ASYNC16(s1 + 0 * GBUF + drow + 16, pAh + go + 16);
            CP_ASYNC16(s1 + 1 * GBUF + drow,      pAl + go);
            CP_ASYNC16(s1 + 1 * GBUF + drow + 16, pAl + go + 16);
            CP_ASYNC16(s1 + 2 * GBUF + drow,      pB + go);
            CP_ASYNC16(s1 + 2 * GBUF + drow + 16, pB + go + 16);
            CP_COMMIT();
            CP_WAIT1();
        } else {
            CP_WAIT0();
        }
        __syncthreads();

        const uint32_t cur = sb + (c & 1) * GSTG;
        const uint32_t sAhi = cur, sAlo = cur + GBUF;
        const uint32_t sB   = cur + 2 * GBUF;

        #pragma unroll
        for (int ks = 0; ks < 32; ks += 16) {
            uint32_t ah[2][4], al[2][4];
            #pragma unroll
            for (int mi = 0; mi < 2; mi++) {
                const int row = warp_m * 32 + mi * 16 + (lane & 15);
                const int col = ks + (lane >> 4) * 8;
                const uint32_t off = (uint32_t)(row * LDSR + col) * 2;
                ldmatrix_x4(ah[mi], sAhi + off);
                ldmatrix_x4(al[mi], sAlo + off);
            }
            #pragma unroll
            for (int ng = 0; ng < 4; ng++) {
                const int nb   = warp_n * 64 + ng * 16;
                const int nrow = nb + (lane & 7) + ((lane >> 4) << 3);
                const int kcol = ks + ((lane >> 3) & 1) * 8;
                const uint32_t off = (uint32_t)(nrow * LDSR + kcol) * 2;
                uint32_t bh[4];
                ldmatrix_x4(bh, sB + off);
                #pragma unroll
                for (int mi = 0; mi < 2; mi++) {
                    #pragma unroll
                    for (int nt = 0; nt < 2; nt++) {
                        float* cc = acc[mi][ng * 2 + nt];
                        mma_fp16(cc, ah[mi], bh + nt * 2);
                        mma_fp16(cc, al[mi], bh + nt * 2);
                    }
                }
            }
        }
        __syncthreads();
    }

    // ---- epilogue ----
    const int g  = lane >> 2;
    const int tg = lane & 3;
    #pragma unroll
    for (int mi = 0; mi < 2; mi++) {
        const int row = m0 + warp_m * 32 + mi * 16 + g;
        #pragma unroll
        for (int nt = 0; nt < 8; nt++) {
            const int col = n0 + warp_n * 64 + nt * 8 + tg * 2;
            if (SPLIT == 1) {
                uint32_t hi, lo;
                split2(acc[mi][nt][0] * alpha, acc[mi][nt][1] * alpha, hi, lo);
                *reinterpret_cast<uint32_t*>(Cbh + (long)row * ldc + col) = hi;
                *reinterpret_cast<uint32_t*>(Cbl + (long)row * ldc + col) = lo;
                split2(acc[mi][nt][2] * alpha, acc[mi][nt][3] * alpha, hi, lo);
                *reinterpret_cast<uint32_t*>(Cbh + (long)(row + 8) * ldc + col) = hi;
                *reinterpret_cast<uint32_t*>(Cbl + (long)(row + 8) * ldc + col) = lo;
            } else if (SPLIT == 2) {
                uint32_t hi, lo;
                split2h(acc[mi][nt][0] * alpha, acc[mi][nt][1] * alpha, hi, lo);
                *reinterpret_cast<uint32_t*>(Chh + (long)row * ldc + col) = hi;
                *reinterpret_cast<uint32_t*>(Chl + (long)row * ldc + col) = lo;
                split2h(acc[mi][nt][2] * alpha, acc[mi][nt][3] * alpha, hi, lo);
                *reinterpret_cast<uint32_t*>(Chh + (long)(row + 8) * ldc + col) = hi;
                *reinterpret_cast<uint32_t*>(Chl + (long)(row + 8) * ldc + col) = lo;
            } else {
                float2 v0, v1;
                v0.x = acc[mi][nt][0]; v0.y = acc[mi][nt][1];
                v1.x = acc[mi][nt][2]; v1.y = acc[mi][nt][3];
                *reinterpret_cast<float2*>(C + (long)row * ldc + col) = v0;
                *reinterpret_cast<float2*>(C + (long)(row + 8) * ldc + col) = v1;
            }
        }
    }
}

// ======================= fused flash attention =============================
// Grid: (SEQ/128, BATCH*HEADS). 256 threads = 8 warps; warp w owns 16 q-rows.
// QK bf16x3; PV fp16x2 (P single fp16, V fp16 hi/lo). O emitted fp16 hi/lo.
#define LDKV 72          // 16-bit-elem row stride (144 B)
#define TILE_B 18432

#define ATT_QH 0
#define ATT_QL TILE_B
#define ATT_ST 36864
#define STG_SZ (4 * TILE_B)
#define ATT_SMEM (ATT_ST + 2 * STG_SZ)   // 184320

__global__ __launch_bounds__(256)
void attn_fused(const __nv_bfloat16* __restrict__ Qh, const __nv_bfloat16* __restrict__ Ql,
                const __nv_bfloat16* __restrict__ Kh, const __nv_bfloat16* __restrict__ Kl,
                const __half* __restrict__ Vh, const __half* __restrict__ Vl,
                __half* __restrict__ Oh, __half* __restrict__ Ol)
{
    extern __shared__ char dsm[];
    const uint32_t sb = smem_u32_of(dsm);

    const int tid  = threadIdx.x;
    const int wid  = tid >> 5;
    const int lane = tid & 31;
    const int g    = lane >> 2;
    const int tg   = lane & 3;

    const int bh = blockIdx.y;
    const int b  = bh >> 4;
    const int h  = bh & 15;
    const int q0 = blockIdx.x * 128;

    const long headoff = (long)h * KDIM;
    const __nv_bfloat16* Qhp = Qh + ((long)(b * SEQ + q0)) * DMODEL + headoff;
    const __nv_bfloat16* Qlp = Ql + ((long)(b * SEQ + q0)) * DMODEL + headoff;
    const __nv_bfloat16* Khp = Kh + ((long)(b * SEQ)) * DMODEL + headoff;
    const __nv_bfloat16* Klp = Kl + ((long)(b * SEQ)) * DMODEL + headoff;
    const __half*        Vhp = Vh + ((long)(b * SEQ)) * DMODEL + headoff;
    const __half*        Vlp = Vl + ((long)(b * SEQ)) * DMODEL + headoff;

    const int row = tid >> 1;
    const int cb  = (tid & 1) * 64;
    const uint32_t drow = (uint32_t)(row * (LDKV * 2)) + cb;

    // ---- issue Q + stage0 K/V ----
    {
        const char* qs_h = (const char*)(Qhp + (long)row * DMODEL) + cb;
        const char* qs_l = (const char*)(Qlp + (long)row * DMODEL) + cb;
        #pragma unroll
        for (int c = 0; c < 4; c++) {
            CP_ASYNC16(sb + ATT_QH + drow + c * 16, qs_h + c * 16);
            CP_ASYNC16(sb + ATT_QL + drow + c * 16, qs_l + c * 16);
        }
        const char* ks_h = (const char*)(Khp + (long)row * DMODEL) + cb;
        const char* ks_l = (const char*)(Klp + (long)row * DMODEL) + cb;
        const char* vs_h = (const char*)(Vhp + (long)row * DMODEL) + cb;
        const char* vs_l = (const char*)(Vlp + (long)row * DMODEL) + cb;
        const uint32_t s0 = sb + ATT_ST;
        #pragma unroll
        for (int c = 0; c < 4; c++) {
            CP_ASYNC16(s0 + 0 * TILE_B + drow + c * 16, ks_h + c * 16);
            CP_ASYNC16(s0 + 1 * TILE_B + drow + c * 16, ks_l + c * 16);
            CP_ASYNC16(s0 + 2 * TILE_B + drow + c * 16, vs_h + c * 16);
            CP_ASYNC16(s0 + 3 * TILE_B + drow + c * 16, vs_l + c * 16);
        }
        CP_COMMIT();
    }

    uint32_t qh[4][4], ql[4][4];
    float m_run[2] = {-1e30f, -1e30f};
    float l_run[2] = {0.f, 0.f};
    float acc_o[8][4];
    #pragma unroll
    for (int i = 0; i < 8; i++)
        #pragma unroll
        for (int q = 0; q < 4; q++) acc_o[i][q] = 0.f;

    const int NT = SEQ / 128;

    for (int t = 0; t < NT; t++) {
        if (t + 1 < NT) {
            const long rbase = (long)((t + 1) * 128 + row) * DMODEL;
            const char* ks_h = (const char*)(Khp + rbase) + cb;
            const char* ks_l = (const char*)(Klp + rbase) + cb;
            const char* vs_h = (const char*)(Vhp + rbase) + cb;
            const char* vs_l = (const char*)(Vlp + rbase) + cb;
            const uint32_t s1 = sb + ATT_ST + ((t + 1) & 1) * STG_SZ;
            #pragma unroll
            for (int c = 0; c < 4; c++) {
                CP_ASYNC16(s1 + 0 * TILE_B + drow + c * 16, ks_h + c * 16);
                CP_ASYNC16(s1 + 1 * TILE_B + drow + c * 16, ks_l + c * 16);
                CP_ASYNC16(s1 + 2 * TILE_B + drow + c * 16, vs_h + c * 16);
                CP_ASYNC16(s1 + 3 * TILE_B + drow + c * 16, vs_l + c * 16);
            }
            CP_COMMIT();
            CP_WAIT1();
        } else {
            CP_WAIT0();
        }
        __syncthreads();

        const uint32_t cur = sb + ATT_ST + (t & 1) * STG_SZ;
        const uint32_t sKh = cur, sKl = cur + TILE_B;
        const uint32_t sVh = cur + 2 * TILE_B, sVl = cur + 3 * TILE_B;

        if (t == 0) {
            #pragma unroll
            for (int ks = 0; ks < 4; ks++) {
                const int qrow = wid * 16 + (lane & 15);
                const int qcol = ks * 16 + (lane >> 4) * 8;
                const uint32_t off = (uint32_t)(qrow * LDKV + qcol) * 2;
                ldmatrix_x4(qh[ks], sb + ATT_QH + off);
                ldmatrix_x4(ql[ks], sb + ATT_QL + off);
            }
        }

        // ---- S = Q K^T (bf16x3) ----
        float s_acc[16][4];
        #pragma unroll
        for (int tt = 0; tt < 16; tt++)
            #pragma unroll
            for (int q = 0; q < 4; q++) s_acc[tt][q] = 0.f;

        #pragma unroll
        for (int ks = 0; ks < 4; ks++) {
            #pragma unroll
            for (int ng = 0; ng < 8; ng++) {
                const int nrow = ng * 16 + (lane & 7) + ((lane >> 4) << 3);
                const int kcol = ks * 16 + ((lane >> 3) & 1) * 8;
                const uint32_t off = (uint32_t)(nrow * LDKV + kcol) * 2;
                uint32_t bh4[4], bl4[4];
                ldmatrix_x4(bh4, sKh + off);
                ldmatrix_x4(bl4, sKl + off);
                #pragma unroll
                for (int nt = 0; nt < 2; nt++) {
                    float* c = s_acc[ng * 2 + nt];
                    mma_bf16(c, qh[ks], bh4 + nt * 2);
                    mma_bf16(c, qh[ks], bl4 + nt * 2);
                    mma_bf16(c, ql[ks], bh4 + nt * 2);
                }
            }
        }

        // ---- online softmax (base-2) ----
        float mnew0 = m_run[0], mnew1 = m_run[1];
        #pragma unroll
        for (int tt = 0; tt < 16; tt++) {
            mnew0 = fmaxf(mnew0, fmaxf(s_acc[tt][0], s_acc[tt][1]));
            mnew1 = fmaxf(mnew1, fmaxf(s_acc[tt][2], s_acc[tt][3]));
        }
        mnew0 = fmaxf(mnew0, __shfl_xor_sync(0xFFFFFFFFu, mnew0, 1));
        mnew0 = fmaxf(mnew0, __shfl_xor_sync(0xFFFFFFFFu, mnew0, 2));
        mnew1 = fmaxf(mnew1, __shfl_xor_sync(0xFFFFFFFFu, mnew1, 1));
        mnew1 = fmaxf(mnew1, __shfl_xor_sync(0xFFFFFFFFu, mnew1, 2));

        const float fac0 = ex2(m_run[0] - mnew0);
        const float fac1 = ex2(m_run[1] - mnew1);
        m_run[0] = mnew0; m_run[1] = mnew1;
        l_run[0] *= fac0; l_run[1] *= fac1;
        #pragma unroll
        for (int i = 0; i < 8; i++) {
            acc_o[i][0] *= fac0; acc_o[i][1] *= fac0;
            acc_o[i][2] *= fac1; acc_o[i][3] *= fac1;
        }

        // ---- P = exp2(S - m); pack single fp16 A-fragments ----
        uint32_t ph[8][4];
        float rs0 = 0.f, rs1 = 0.f;
        #pragma unroll
        for (int tt = 0; tt < 16; tt++) {
            const float p0 = ex2(s_acc[tt][0] - mnew0);
            const float p1 = ex2(s_acc[tt][1] - mnew0);
            const float p2 = ex2(s_acc[tt][2] - mnew1);
            const float p3 = ex2(s_acc[tt][3] - mnew1);
            rs0 += p0 + p1;
            rs1 += p2 + p3;
            const int kk = tt >> 1, half = tt & 1;
            ph[kk][2 * half]     = pack2h(p0, p1);
            ph[kk][2 * half + 1] = pack2h(p2, p3);
        }
        rs0 += __shfl_xor_sync(0xFFFFFFFFu, rs0, 1);
        rs0 += __shfl_xor_sync(0xFFFFFFFFu, rs0, 2);
        rs1 += __shfl_xor_sync(0xFFFFFFFFu, rs1, 1);
        rs1 += __shfl_xor_sync(0xFFFFFFFFu, rs1, 2);
        l_run[0] += rs0; l_run[1] += rs1;

        // ---- O += P V (fp16x2: p*vh + p*vl) ----
        #pragma unroll
        for (int kk = 0; kk < 8; kk++) {
            #pragma unroll
            for (int ndp = 0; ndp < 4; ndp++) {
                const int krow = kk * 16 + ((lane >> 3) & 1) * 8 + (lane & 7);
                const int ncol = ndp * 16 + ((lane >> 4) << 3);
                const uint32_t off = (uint32_t)(krow * LDKV + ncol) * 2;
                uint32_t vh4[4], vl4[4];
                ldmatrix_x4_t(vh4, sVh + off);
                ldmatrix_x4_t(vl4, sVl + off);
                #pragma unroll
                for (int nt = 0; nt < 2; nt++) {
                    float* c = acc_o[ndp * 2 + nt];
                    mma_fp16(c, ph[kk], vh4 + nt * 2);
                    mma_fp16(c, ph[kk], vl4 + nt * 2);
                }
            }
        }
        __syncthreads();
    }

    // ---- epilogue: O /= l, write pre-split fp16 hi/lo ----
    const float inv0 = 1.0f / l_run[0];
    const float inv1 = 1.0f / l_run[1];
    const long row0 = (long)(b * SEQ + q0 + wid * 16 + g);
    #pragma unroll
    for (int nt = 0; nt < 8; nt++) {
        const int col = h * KDIM + nt * 8 + tg * 2;
        uint32_t hi, lo;
        split2h(acc_o[nt][0] * inv0, acc_o[nt][1] * inv0, hi, lo);
        *reinterpret_cast<uint32_t*>(Oh + row0 * DMODEL + col) = hi;
        *reinterpret_cast<uint32_t*>(Ol + row0 * DMODEL + col) = lo;
        split2h(acc_o[nt][2] * inv1, acc_o[nt][3] * inv1, hi, lo);
        *reinterpret_cast<uint32_t*>(Oh + (row0 + 8) * DMODEL + col) = hi;
        *reinterpret_cast<uint32_t*>(Ol + (row0 + 8) * DMODEL + col) = lo;
    }
}

// ---------------------------------------------------------------------------
extern "C" void kernel_launch(void* const* d_in, const int* in_sizes, int n_in,
                              void* d_out, int out_size)
{
    const float* X  = (const float*)d_in[0];
    const float* Wq = (const float*)d_in[1];
    const float* Wk = (const float*)d_in[2];
    const float* Wv = (const float*)d_in[3];
    const float* Wo = (const float*)d_in[4];
    float* out = (float*)d_out;

    __half *Xh, *Xl, *W, *Vh, *Vl, *Oh, *Ol;
    __nv_bfloat16 *Qh, *Ql, *Kh, *Kl;
    cudaGetSymbolAddress((void**)&Xh, g_Xh);
    cudaGetSymbolAddress((void**)&Xl, g_Xl);
    cudaGetSymbolAddress((void**)&W,  g_W);
    cudaGetSymbolAddress((void**)&Qh, g_Qh);
    cudaGetSymbolAddress((void**)&Ql, g_Ql);
    cudaGetSymbolAddress((void**)&Kh, g_Kh);
    cudaGetSymbolAddress((void**)&Kl, g_Kl);
    cudaGetSymbolAddress((void**)&Vh, g_Vh);
    cudaGetSymbolAddress((void**)&Vl, g_Vl);
    cudaGetSymbolAddress((void**)&Oh, g_Oh);
    cudaGetSymbolAddress((void**)&Ol, g_Ol);

    cudaFuncSetAttribute(attn_fused,
                         cudaFuncAttributeMaxDynamicSharedMemorySize, ATT_SMEM);
    cudaFuncSetAttribute(gemm_f2<0>,
                         cudaFuncAttributeMaxDynamicSharedMemorySize, GSMEM);
    cudaFuncSetAttribute(gemm_f2<1>,
                         cudaFuncAttributeMaxDynamicSharedMemorySize, GSMEM);
    cudaFuncSetAttribute(gemm_f2<2>,
                         cudaFuncAttributeMaxDynamicSharedMemorySize, GSMEM);

    const float SC = 0.125f * 1.4426950408889634f;
    const int WSZ = DMODEL * DMODEL;

    // --- 0) pre-split X (fp16 hi/lo) and round weights (fp16) ---
    {
        const int n4x = MTOT * DMODEL / 4;
        conv_split_h<<<n4x / 256, 256>>>(X, Xh, Xl, n4x);
        const int n4w = WSZ / 4;
        conv_h<<<n4w / 256, 256>>>(Wq, W + 0L * WSZ, n4w);
        conv_h<<<n4w / 256, 256>>>(Wk, W + 1L * WSZ, n4w);
        conv_h<<<n4w / 256, 256>>>(Wv, W + 2L * WSZ, n4w);
        conv_h<<<n4w / 256, 256>>>(Wo, W + 3L * WSZ, n4w);
    }

    // --- 1) Projections (fp16x2; Q pre-scaled; Q/K emitted bf16, V fp16) ---
    {
        dim3 grid(DMODEL / 128, MTOT / 128);
        gemm_f2<1><<<grid, 256, GSMEM>>>(Xh, Xl, W + 0L * WSZ,
            nullptr, Qh, Ql, nullptr, nullptr, SC, DMODEL, DMODEL, DMODEL, DMODEL);
        gemm_f2<1><<<grid, 256, GSMEM>>>(Xh, Xl, W + 1L * WSZ,
            nullptr, Kh, Kl, nullptr, nullptr, 1.0f, DMODEL, DMODEL, DMODEL, DMODEL);
        gemm_f2<2><<<grid, 256, GSMEM>>>(Xh, Xl, W + 2L * WSZ,
            nullptr, nullptr, nullptr, Vh, Vl, 1.0f, DMODEL, DMODEL, DMODEL, DMODEL);
    }

    // --- 2) Fused attention (writes pre-split fp16 O) ---
    {
        dim3 grid(SEQ / 128, BATCH * HEADS);
        attn_fused<<<grid, 256, ATT_SMEM>>>(Qh, Ql, Kh, Kl, Vh, Vl, Oh, Ol);
    }

    // --- 3) out = O @ Wo^T (fp32 out) ---
    {
        dim3 grid(DMODEL / 128, MTOT / 128);
        gemm_f2<0><<<grid, 256, GSMEM>>>(Oh, Ol, W + 3L * WSZ,
            out, nullptr, nullptr, nullptr, nullptr, 1.0f, DMODEL, DMODEL, DMODEL, DMODEL);
    }
}